// round 5
// baseline (speedup 1.0000x reference)
#include <cuda_runtime.h>
#include <cuda_fp16.h>
#include <cstdint>
#include <math.h>

// ---------------- problem constants ----------------
#define T_DIM 512
#define B_DIM 64
#define E_DIM 300
#define H_DIM 800
#define L_DIM 3
#define M_DIM (T_DIM * B_DIM)   // 32768
#define N_OUT 2400              // 3*H
#define N_PADROWS 2432          // N padded to mult of 128
#define KPAD0 320               // 300 -> mult of 32
#define KPAD  832               // 800 -> mult of 32

// scan chunking
#define NCH 8
#define TC  (T_DIM / NCH)       // 64

// GEMM tiling
#define BM 256
#define BN 128
#define BK 32
#define STAGES 3
#define STAGE_BYTES 32768       // A 16K | Bh 8K | Bl 8K
#define A_OFF  0
#define BH_OFF 16384
#define BL_OFF 24576
#define WSCALE 32.0f
#define INV_WSCALE (1.0f / 32.0f)

// ---------------- static scratch ----------------
__device__ __half g_buf[(size_t)M_DIM * N_OUT];           // post-activation z|f|o (fp16)
__device__ __half A0_buf[(size_t)M_DIM * KPAD0];          // layer0 A operand
__device__ __half A12_buf[(size_t)M_DIM * KPAD];          // layers 1/2 A operand (h)
__device__ __half W0h_buf[(size_t)N_PADROWS * KPAD0];
__device__ __half W0l_buf[(size_t)N_PADROWS * KPAD0];
__device__ __half W1h_buf[(size_t)N_PADROWS * KPAD];
__device__ __half W1l_buf[(size_t)N_PADROWS * KPAD];
__device__ __half W2h_buf[(size_t)N_PADROWS * KPAD];
__device__ __half W2l_buf[(size_t)N_PADROWS * KPAD];
__device__ float Pc_buf[(size_t)NCH * B_DIM * H_DIM];     // per-chunk product of (1-f)
__device__ float Cc_buf[(size_t)NCH * B_DIM * H_DIM];     // per-chunk local final c

// ---------------- helpers ----------------
__device__ __forceinline__ uint32_t smem_u32(const void* p) {
    uint32_t a;
    asm("{ .reg .u64 t; cvta.to.shared.u64 t, %1; cvt.u32.u64 %0, t; }" : "=r"(a) : "l"(p));
    return a;
}
__device__ __forceinline__ void cp16(uint32_t dst, const void* src) {
    asm volatile("cp.async.cg.shared.global [%0], [%1], 16;" :: "r"(dst), "l"(src) : "memory");
}
__device__ __forceinline__ void cp_commit() {
    asm volatile("cp.async.commit_group;" ::: "memory");
}
template <int N> __device__ __forceinline__ void cp_wait() {
    asm volatile("cp.async.wait_group %0;" :: "n"(N) : "memory");
}
__device__ __forceinline__ void ldsm4(uint32_t& r0, uint32_t& r1, uint32_t& r2, uint32_t& r3,
                                      uint32_t addr) {
    asm volatile("ldmatrix.sync.aligned.m8n8.x4.shared.b16 {%0,%1,%2,%3}, [%4];"
                 : "=r"(r0), "=r"(r1), "=r"(r2), "=r"(r3) : "r"(addr));
}
__device__ __forceinline__ void mma_f16(float* c, const uint32_t* a, const uint32_t* b) {
    asm volatile(
        "mma.sync.aligned.m16n8k16.row.col.f32.f16.f16.f32 "
        "{%0,%1,%2,%3}, {%4,%5,%6,%7}, {%8,%9}, {%0,%1,%2,%3};"
        : "+f"(c[0]), "+f"(c[1]), "+f"(c[2]), "+f"(c[3])
        : "r"(a[0]), "r"(a[1]), "r"(a[2]), "r"(a[3]), "r"(b[0]), "r"(b[1]));
}
__device__ __forceinline__ float sigmoidf_(float x) { return 1.f / (1.f + __expf(-x)); }
__device__ __forceinline__ float tanhf_(float x)    { return 1.f - 2.f / (__expf(2.f * x) + 1.f); }

// ---------------- weight transpose + fp16 split (scaled x32): W[K,N] -> Wt[Np,Kp] hi/lo ----
__global__ void conv_w_kernel(const float* __restrict__ W,
                              __half* __restrict__ Th, __half* __restrict__ Tl,
                              int K, int Kp) {
    __shared__ float tile[32][33];
    int kb = blockIdx.y * 32, nb = blockIdx.x * 32;
    for (int r = threadIdx.y; r < 32; r += 8) {
        int k = kb + r, n = nb + threadIdx.x;
        tile[r][threadIdx.x] = (k < K && n < N_OUT) ? W[(size_t)k * N_OUT + n] : 0.f;
    }
    __syncthreads();
    for (int r = threadIdx.y; r < 32; r += 8) {
        int n = nb + r, k = kb + threadIdx.x;
        float v = tile[threadIdx.x][r] * WSCALE;
        __half hi = __float2half(v);
        Th[(size_t)n * Kp + k] = hi;
        Tl[(size_t)n * Kp + k] = __float2half(v - __half2float(hi));
    }
}

// ---------------- sent fp32 -> fp16 (padded K) ----------------
__global__ void conv_sent_kernel(const float* __restrict__ x) {
    size_t i = (size_t)blockIdx.x * 256 + threadIdx.x;
    if (i >= (size_t)M_DIM * KPAD0) return;
    size_t row = i / KPAD0;
    int j = (int)(i % KPAD0);
    A0_buf[i] = __float2half((j < E_DIM) ? x[row * E_DIM + j] : 0.f);
}

// ---------------- fp16x2 HMMA GEMM (256x128 tile) with fused bias + activation ----------
// g[m,n] = act( (1/32) * sum_k A[m,k]*(Wh+Wl)[n,k] + bias[n] ), stored fp16
__global__ __launch_bounds__(256, 1)
void qrnn_gemm_kernel(const __half* __restrict__ A,
                      const __half* __restrict__ Bh, const __half* __restrict__ Bl,
                      int ldk, int nc,
                      const float* __restrict__ bias, __half* __restrict__ C) {
    extern __shared__ char smem[];
    const uint32_t sbase = smem_u32(smem);

    const int tid = threadIdx.x;
    const int lane = tid & 31;
    const int wid = tid >> 5;
    const int wm = wid & 1;           // 2 M-slabs of 128 rows
    const int wn = wid >> 1;          // 4 N-slabs of 32 cols
    const int am0 = blockIdx.y * BM;
    const int bn0 = blockIdx.x * BN;

    auto load_stage = [&](int kc, int st) {
        const size_t kof = (size_t)kc * BK;
        uint32_t sb = sbase + st * STAGE_BYTES;
#pragma unroll
        for (int i = 0; i < 4; i++) {          // A: 1024 16B chunks (256 rows)
            int id = tid + i * 256;
            int row = id >> 2, c = id & 3;
            int sc = c ^ ((row >> 1) & 3);
            cp16(sb + A_OFF + row * 64 + sc * 16,
                 A + (size_t)(am0 + row) * ldk + kof + (size_t)c * 8);
        }
#pragma unroll
        for (int i = 0; i < 2; i++) {          // B: 512 chunks each (128 rows)
            int id = tid + i * 256;
            int row = id >> 2, c = id & 3;
            int sc = c ^ ((row >> 1) & 3);
            uint32_t soff = row * 64 + sc * 16;
            size_t gb = (size_t)(bn0 + row) * ldk + kof + (size_t)c * 8;
            cp16(sb + BH_OFF + soff, Bh + gb);
            cp16(sb + BL_OFF + soff, Bl + gb);
        }
    };

    float acc[8][4][4];
#pragma unroll
    for (int i = 0; i < 8; i++)
#pragma unroll
        for (int j = 0; j < 4; j++)
#pragma unroll
            for (int q = 0; q < 4; q++) acc[i][j][q] = 0.f;

    load_stage(0, 0); cp_commit();
    if (nc > 1) { load_stage(1, 1); cp_commit(); }

    const int lr = lane & 15;
    const int lc = lane >> 4;

    for (int kc = 0; kc < nc; kc++) {
        if (kc + 1 < nc) cp_wait<1>(); else cp_wait<0>();
        __syncthreads();
        if (kc + 2 < nc) { load_stage(kc + 2, (kc + 2) % STAGES); cp_commit(); }

        uint32_t sb = sbase + (kc % STAGES) * STAGE_BYTES;
#pragma unroll
        for (int kk = 0; kk < 2; kk++) {
            uint32_t bh[4][2], bl[4][2];
#pragma unroll
            for (int p = 0; p < 2; p++) {
                int rowb = wn * 32 + p * 16 + lr;
                uint32_t off = rowb * 64 + (((kk * 2 + lc) ^ ((rowb >> 1) & 3)) * 16);
                uint32_t r0, r1, r2, r3;
                ldsm4(r0, r1, r2, r3, sb + BH_OFF + off);
                bh[2 * p][0] = r0; bh[2 * p + 1][0] = r1;
                bh[2 * p][1] = r2; bh[2 * p + 1][1] = r3;
                ldsm4(r0, r1, r2, r3, sb + BL_OFF + off);
                bl[2 * p][0] = r0; bl[2 * p + 1][0] = r1;
                bl[2 * p][1] = r2; bl[2 * p + 1][1] = r3;
            }
#pragma unroll
            for (int mt = 0; mt < 8; mt++) {
                int rowa = wm * 128 + mt * 16 + lr;
                uint32_t off = rowa * 64 + (((kk * 2 + lc) ^ ((rowa >> 1) & 3)) * 16);
                uint32_t a[4];
                ldsm4(a[0], a[1], a[2], a[3], sb + A_OFF + off);
#pragma unroll
                for (int ng = 0; ng < 4; ng++) {
                    mma_f16(acc[mt][ng], a, bh[ng]);
                    mma_f16(acc[mt][ng], a, bl[ng]);
                }
            }
        }
        __syncthreads();
    }

    // ---- epilogue: unscale + bias + activation, half2 stores ----
    const int tg = lane >> 2;
    const int tq = lane & 3;
#pragma unroll
    for (int ng = 0; ng < 4; ng++) {
        int colb = bn0 + wn * 32 + ng * 8;
        if (colb >= N_OUT) continue;
        int col = colb + tq * 2;
        float2 bv = *reinterpret_cast<const float2*>(&bias[col]);
        bool is_t = colb < H_DIM;
#pragma unroll
        for (int mt = 0; mt < 8; mt++) {
            int r0 = am0 + wm * 128 + mt * 16 + tg;
            float x0 = acc[mt][ng][0] * INV_WSCALE + bv.x;
            float x1 = acc[mt][ng][1] * INV_WSCALE + bv.y;
            float x2 = acc[mt][ng][2] * INV_WSCALE + bv.x;
            float x3 = acc[mt][ng][3] * INV_WSCALE + bv.y;
            float v0 = is_t ? tanhf_(x0) : sigmoidf_(x0);
            float v1 = is_t ? tanhf_(x1) : sigmoidf_(x1);
            float v2 = is_t ? tanhf_(x2) : sigmoidf_(x2);
            float v3 = is_t ? tanhf_(x3) : sigmoidf_(x3);
            *reinterpret_cast<__half2*>(&C[(size_t)r0 * N_OUT + col]) =
                __floats2half2_rn(v0, v1);
            *reinterpret_cast<__half2*>(&C[(size_t)(r0 + 8) * N_OUT + col]) =
                __floats2half2_rn(v2, v3);
        }
    }
}

// ---------------- scan phase 1: per-chunk (prod(1-f), local c) ----------------
__global__ __launch_bounds__(256)
void scan_phase1_kernel(const __half* __restrict__ g) {
    int idx = blockIdx.x * 256 + threadIdx.x;
    if (idx >= NCH * B_DIM * H_DIM) return;
    int j = idx % H_DIM;
    int b = (idx / H_DIM) % B_DIM;
    int ch = idx / (H_DIM * B_DIM);

    const __half* gp = g + (size_t)b * N_OUT + j;
    float c = 0.f, P = 1.f;
    int t0b = ch * TC;
    for (int t0 = t0b; t0 < t0b + TC; t0 += 4) {
        float zt[4], fs[4];
#pragma unroll
        for (int u = 0; u < 4; u++) {
            size_t base = (size_t)(t0 + u) * B_DIM * N_OUT;
            zt[u] = __half2float(gp[base]);
            fs[u] = __half2float(gp[base + H_DIM]);
        }
#pragma unroll
        for (int u = 0; u < 4; u++) {
            c = fmaf(fs[u], zt[u] - c, c);
            P *= (1.f - fs[u]);
        }
    }
    Pc_buf[idx] = P;
    Cc_buf[idx] = c;
}

// ---------------- scan phase 2: prefix + re-scan, write h (fp16) + final c ----------------
__global__ __launch_bounds__(256)
void scan_phase2_kernel(const __half* __restrict__ g, __half* __restrict__ H,
                        float* __restrict__ out, int layer, int write_h) {
    int idx = blockIdx.x * 256 + threadIdx.x;
    if (idx >= NCH * B_DIM * H_DIM) return;
    int j = idx % H_DIM;
    int b = (idx / H_DIM) % B_DIM;
    int ch = idx / (H_DIM * B_DIM);

    float c = 0.f;
    for (int i = 0; i < ch; i++) {
        size_t o = ((size_t)i * B_DIM + b) * H_DIM + j;
        c = Cc_buf[o] + Pc_buf[o] * c;
    }

    const __half* gp = g + (size_t)b * N_OUT + j;
    int t0b = ch * TC;
    for (int t0 = t0b; t0 < t0b + TC; t0 += 4) {
        float zt[4], fs[4], os[4];
#pragma unroll
        for (int u = 0; u < 4; u++) {
            size_t base = (size_t)(t0 + u) * B_DIM * N_OUT;
            zt[u] = __half2float(gp[base]);
            fs[u] = __half2float(gp[base + H_DIM]);
            os[u] = __half2float(gp[base + 2 * H_DIM]);
        }
#pragma unroll
        for (int u = 0; u < 4; u++) {
            c = fmaf(fs[u], zt[u] - c, c);
            if (write_h)
                H[(size_t)((t0 + u) * B_DIM + b) * KPAD + j] = __float2half(os[u] * c);
        }
    }
    if (ch == NCH - 1)
        out[(size_t)b * (L_DIM * H_DIM) + (size_t)layer * H_DIM + j] = c;
}

// ---------------- launch ----------------
extern "C" void kernel_launch(void* const* d_in, const int* in_sizes, int n_in,
                              void* d_out, int out_size) {
    const float* sent = (const float*)d_in[0];
    const float* W0 = (const float*)d_in[2];
    const float* b0 = (const float*)d_in[3];
    const float* W1 = (const float*)d_in[4];
    const float* b1 = (const float*)d_in[5];
    const float* W2 = (const float*)d_in[6];
    const float* b2 = (const float*)d_in[7];
    float* out = (float*)d_out;

    __half* g;  cudaGetSymbolAddress((void**)&g, g_buf);
    __half *a0, *a12, *w0h, *w0l, *w1h, *w1l, *w2h, *w2l;
    cudaGetSymbolAddress((void**)&a0, A0_buf);
    cudaGetSymbolAddress((void**)&a12, A12_buf);
    cudaGetSymbolAddress((void**)&w0h, W0h_buf); cudaGetSymbolAddress((void**)&w0l, W0l_buf);
    cudaGetSymbolAddress((void**)&w1h, W1h_buf); cudaGetSymbolAddress((void**)&w1l, W1l_buf);
    cudaGetSymbolAddress((void**)&w2h, W2h_buf); cudaGetSymbolAddress((void**)&w2l, W2l_buf);

    cudaFuncSetAttribute(qrnn_gemm_kernel, cudaFuncAttributeMaxDynamicSharedMemorySize,
                         STAGES * STAGE_BYTES);

    // zero A12 so its K-padding columns (800..831) stay 0 across layers
    cudaMemsetAsync(a12, 0, (size_t)M_DIM * KPAD * sizeof(__half), 0);

    dim3 wblk(32, 8);
    dim3 wgrid0(N_PADROWS / 32, KPAD0 / 32);
    dim3 wgrid12(N_PADROWS / 32, KPAD / 32);
    conv_w_kernel<<<wgrid0, wblk>>>(W0, w0h, w0l, E_DIM, KPAD0);
    conv_w_kernel<<<wgrid12, wblk>>>(W1, w1h, w1l, H_DIM, KPAD);
    conv_w_kernel<<<wgrid12, wblk>>>(W2, w2h, w2l, H_DIM, KPAD);

    {
        size_t n = (size_t)M_DIM * KPAD0;
        conv_sent_kernel<<<(unsigned)((n + 255) / 256), 256>>>(sent);
    }

    dim3 ggrid(N_PADROWS / BN, M_DIM / BM);   // (19, 128)
    size_t smem = STAGES * STAGE_BYTES;
    int scan_total = NCH * B_DIM * H_DIM;
    int scan_blocks = (scan_total + 255) / 256;

    qrnn_gemm_kernel<<<ggrid, 256, smem>>>(a0, w0h, w0l, KPAD0, KPAD0 / BK, b0, g);
    scan_phase1_kernel<<<scan_blocks, 256>>>(g);
    scan_phase2_kernel<<<scan_blocks, 256>>>(g, a12, out, 0, 1);

    qrnn_gemm_kernel<<<ggrid, 256, smem>>>(a12, w1h, w1l, KPAD, KPAD / BK, b1, g);
    scan_phase1_kernel<<<scan_blocks, 256>>>(g);
    scan_phase2_kernel<<<scan_blocks, 256>>>(g, a12, out, 1, 1);

    qrnn_gemm_kernel<<<ggrid, 256, smem>>>(a12, w2h, w2l, KPAD, KPAD / BK, b2, g);
    scan_phase1_kernel<<<scan_blocks, 256>>>(g);
    scan_phase2_kernel<<<scan_blocks, 256>>>(g, a12, out, 2, 0);
}

// round 6
// speedup vs baseline: 1.9043x; 1.9043x over previous
#include <cuda_runtime.h>
#include <cuda_fp16.h>
#include <cstdint>
#include <math.h>

// ---------------- problem constants ----------------
#define T_DIM 512
#define B_DIM 64
#define E_DIM 300
#define H_DIM 800
#define L_DIM 3
#define M_DIM (T_DIM * B_DIM)   // 32768
#define N_OUT 2400              // 3*H
#define N_PADROWS 2432          // N padded to mult of 128
#define KPAD0 320               // 300 -> mult of 32
#define KPAD  832               // 800 -> mult of 32

// scan chunking
#define NCH 8
#define TC  (T_DIM / NCH)       // 64

// GEMM tiling (round-4 proven shape)
#define BM 128
#define BN 128
#define BK 32
#define STAGES 3
#define STAGE_BYTES 24576       // A 8K | Bh 8K | Bl 8K
#define A_OFF  0
#define BH_OFF 8192
#define BL_OFF 16384
#define WSCALE 32.0f
#define INV_WSCALE (1.0f / 32.0f)

// ---------------- static scratch ----------------
__device__ __half g_buf[(size_t)M_DIM * N_OUT];           // post-activation z|f|o (fp16)
__device__ __half A0_buf[(size_t)M_DIM * KPAD0];          // layer0 A operand
__device__ __half A12_buf[(size_t)M_DIM * KPAD];          // layers 1/2 A operand (h)
__device__ __half W0h_buf[(size_t)N_PADROWS * KPAD0];
__device__ __half W0l_buf[(size_t)N_PADROWS * KPAD0];
__device__ __half W1h_buf[(size_t)N_PADROWS * KPAD];
__device__ __half W1l_buf[(size_t)N_PADROWS * KPAD];
__device__ __half W2h_buf[(size_t)N_PADROWS * KPAD];
__device__ __half W2l_buf[(size_t)N_PADROWS * KPAD];
__device__ float Pc_buf[(size_t)NCH * B_DIM * H_DIM];     // per-chunk product of (1-f)
__device__ float Cc_buf[(size_t)NCH * B_DIM * H_DIM];     // per-chunk local final c

// ---------------- helpers ----------------
__device__ __forceinline__ uint32_t smem_u32(const void* p) {
    uint32_t a;
    asm("{ .reg .u64 t; cvta.to.shared.u64 t, %1; cvt.u32.u64 %0, t; }" : "=r"(a) : "l"(p));
    return a;
}
__device__ __forceinline__ void cp16(uint32_t dst, const void* src) {
    asm volatile("cp.async.cg.shared.global [%0], [%1], 16;" :: "r"(dst), "l"(src) : "memory");
}
__device__ __forceinline__ void cp_commit() {
    asm volatile("cp.async.commit_group;" ::: "memory");
}
template <int N> __device__ __forceinline__ void cp_wait() {
    asm volatile("cp.async.wait_group %0;" :: "n"(N) : "memory");
}
__device__ __forceinline__ void ldsm4(uint32_t& r0, uint32_t& r1, uint32_t& r2, uint32_t& r3,
                                      uint32_t addr) {
    asm volatile("ldmatrix.sync.aligned.m8n8.x4.shared.b16 {%0,%1,%2,%3}, [%4];"
                 : "=r"(r0), "=r"(r1), "=r"(r2), "=r"(r3) : "r"(addr));
}
__device__ __forceinline__ void mma_f16(float* c, const uint32_t* a, const uint32_t* b) {
    asm volatile(
        "mma.sync.aligned.m16n8k16.row.col.f32.f16.f16.f32 "
        "{%0,%1,%2,%3}, {%4,%5,%6,%7}, {%8,%9}, {%0,%1,%2,%3};"
        : "+f"(c[0]), "+f"(c[1]), "+f"(c[2]), "+f"(c[3])
        : "r"(a[0]), "r"(a[1]), "r"(a[2]), "r"(a[3]), "r"(b[0]), "r"(b[1]));
}
__device__ __forceinline__ float sigmoidf_(float x) { return 1.f / (1.f + __expf(-x)); }
__device__ __forceinline__ float tanhf_(float x)    { return 1.f - 2.f / (__expf(2.f * x) + 1.f); }

// ---------------- weight transpose + fp16 split (scaled x32): W[K,N] -> Wt[Np,Kp] hi/lo ----
__global__ void conv_w_kernel(const float* __restrict__ W,
                              __half* __restrict__ Th, __half* __restrict__ Tl,
                              int K, int Kp) {
    __shared__ float tile[32][33];
    int kb = blockIdx.y * 32, nb = blockIdx.x * 32;
    for (int r = threadIdx.y; r < 32; r += 8) {
        int k = kb + r, n = nb + threadIdx.x;
        tile[r][threadIdx.x] = (k < K && n < N_OUT) ? W[(size_t)k * N_OUT + n] : 0.f;
    }
    __syncthreads();
    for (int r = threadIdx.y; r < 32; r += 8) {
        int n = nb + r, k = kb + threadIdx.x;
        float v = tile[threadIdx.x][r] * WSCALE;
        __half hi = __float2half(v);
        Th[(size_t)n * Kp + k] = hi;
        Tl[(size_t)n * Kp + k] = __float2half(v - __half2float(hi));
    }
}

// ---------------- sent fp32 -> fp16 (padded K) ----------------
__global__ void conv_sent_kernel(const float* __restrict__ x) {
    size_t i = (size_t)blockIdx.x * 256 + threadIdx.x;
    if (i >= (size_t)M_DIM * KPAD0) return;
    size_t row = i / KPAD0;
    int j = (int)(i % KPAD0);
    A0_buf[i] = __float2half((j < E_DIM) ? x[row * E_DIM + j] : 0.f);
}

// ---------------- fp16x2 HMMA GEMM (128x128 tile) with fused bias + activation ----------
// g[m,n] = act( (1/32) * sum_k A[m,k]*(Wh+Wl)[n,k] + bias[n] ), stored fp16
__global__ __launch_bounds__(256, 2)
void qrnn_gemm_kernel(const __half* __restrict__ A,
                      const __half* __restrict__ Bh, const __half* __restrict__ Bl,
                      int ldk, int nc,
                      const float* __restrict__ bias, __half* __restrict__ C) {
    extern __shared__ char smem[];
    const uint32_t sbase = smem_u32(smem);

    const int tid = threadIdx.x;
    const int lane = tid & 31;
    const int wid = tid >> 5;
    const int wm = wid >> 2;          // 0..1 -> 64-row slabs
    const int wn = wid & 3;           // 0..3 -> 32-col slabs
    const int am0 = blockIdx.y * BM;
    const int bn0 = blockIdx.x * BN;

    auto load_stage = [&](int kc, int st) {
        const size_t kof = (size_t)kc * BK;
        uint32_t sb = sbase + st * STAGE_BYTES;
#pragma unroll
        for (int i = 0; i < 2; i++) {
            int id = tid + i * 256;        // 0..511
            int row = id >> 2, c = id & 3;
            int sc = c ^ ((row >> 1) & 3);
            uint32_t soff = row * 64 + sc * 16;
            size_t ga = (size_t)(am0 + row) * ldk + kof + (size_t)c * 8;
            size_t gb = (size_t)(bn0 + row) * ldk + kof + (size_t)c * 8;
            cp16(sb + A_OFF + soff, A + ga);
            cp16(sb + BH_OFF + soff, Bh + gb);
            cp16(sb + BL_OFF + soff, Bl + gb);
        }
    };

    float acc[4][4][4];
#pragma unroll
    for (int i = 0; i < 4; i++)
#pragma unroll
        for (int j = 0; j < 4; j++)
#pragma unroll
            for (int q = 0; q < 4; q++) acc[i][j][q] = 0.f;

    load_stage(0, 0); cp_commit();
    if (nc > 1) { load_stage(1, 1); cp_commit(); }

    const int lr = lane & 15;
    const int lc = lane >> 4;

    for (int kc = 0; kc < nc; kc++) {
        if (kc + 1 < nc) cp_wait<1>(); else cp_wait<0>();
        __syncthreads();
        if (kc + 2 < nc) { load_stage(kc + 2, (kc + 2) % STAGES); cp_commit(); }

        uint32_t sb = sbase + (kc % STAGES) * STAGE_BYTES;
#pragma unroll
        for (int kk = 0; kk < 2; kk++) {
            uint32_t bh[4][2], bl[4][2];
#pragma unroll
            for (int p = 0; p < 2; p++) {
                int rowb = wn * 32 + p * 16 + lr;
                uint32_t off = rowb * 64 + (((kk * 2 + lc) ^ ((rowb >> 1) & 3)) * 16);
                uint32_t r0, r1, r2, r3;
                ldsm4(r0, r1, r2, r3, sb + BH_OFF + off);
                bh[2 * p][0] = r0; bh[2 * p + 1][0] = r1;
                bh[2 * p][1] = r2; bh[2 * p + 1][1] = r3;
                ldsm4(r0, r1, r2, r3, sb + BL_OFF + off);
                bl[2 * p][0] = r0; bl[2 * p + 1][0] = r1;
                bl[2 * p][1] = r2; bl[2 * p + 1][1] = r3;
            }
#pragma unroll
            for (int mt = 0; mt < 4; mt++) {
                int rowa = wm * 64 + mt * 16 + lr;
                uint32_t off = rowa * 64 + (((kk * 2 + lc) ^ ((rowa >> 1) & 3)) * 16);
                uint32_t a[4];
                ldsm4(a[0], a[1], a[2], a[3], sb + A_OFF + off);
#pragma unroll
                for (int ng = 0; ng < 4; ng++) {
                    mma_f16(acc[mt][ng], a, bh[ng]);
                    mma_f16(acc[mt][ng], a, bl[ng]);
                }
            }
        }
        __syncthreads();
    }

    // ---- epilogue: unscale + bias + activation, half2 stores ----
    const int tg = lane >> 2;
    const int tq = lane & 3;
#pragma unroll
    for (int ng = 0; ng < 4; ng++) {
        int colb = bn0 + wn * 32 + ng * 8;
        if (colb >= N_OUT) continue;
        int col = colb + tq * 2;
        float2 bv = *reinterpret_cast<const float2*>(&bias[col]);
        bool is_t = colb < H_DIM;
#pragma unroll
        for (int mt = 0; mt < 4; mt++) {
            int r0 = am0 + wm * 64 + mt * 16 + tg;
            float x0 = acc[mt][ng][0] * INV_WSCALE + bv.x;
            float x1 = acc[mt][ng][1] * INV_WSCALE + bv.y;
            float x2 = acc[mt][ng][2] * INV_WSCALE + bv.x;
            float x3 = acc[mt][ng][3] * INV_WSCALE + bv.y;
            float v0 = is_t ? tanhf_(x0) : sigmoidf_(x0);
            float v1 = is_t ? tanhf_(x1) : sigmoidf_(x1);
            float v2 = is_t ? tanhf_(x2) : sigmoidf_(x2);
            float v3 = is_t ? tanhf_(x3) : sigmoidf_(x3);
            *reinterpret_cast<__half2*>(&C[(size_t)r0 * N_OUT + col]) =
                __floats2half2_rn(v0, v1);
            *reinterpret_cast<__half2*>(&C[(size_t)(r0 + 8) * N_OUT + col]) =
                __floats2half2_rn(v2, v3);
        }
    }
}

// ---------------- scan phase 1: per-chunk (prod(1-f), local c) ----------------
__global__ __launch_bounds__(256)
void scan_phase1_kernel(const __half* __restrict__ g) {
    int idx = blockIdx.x * 256 + threadIdx.x;
    if (idx >= NCH * B_DIM * H_DIM) return;
    int j = idx % H_DIM;
    int b = (idx / H_DIM) % B_DIM;
    int ch = idx / (H_DIM * B_DIM);

    const __half* gp = g + (size_t)b * N_OUT + j;
    float c = 0.f, P = 1.f;
    int t0b = ch * TC;
    for (int t0 = t0b; t0 < t0b + TC; t0 += 4) {
        float zt[4], fs[4];
#pragma unroll
        for (int u = 0; u < 4; u++) {
            size_t base = (size_t)(t0 + u) * B_DIM * N_OUT;
            zt[u] = __half2float(gp[base]);
            fs[u] = __half2float(gp[base + H_DIM]);
        }
#pragma unroll
        for (int u = 0; u < 4; u++) {
            c = fmaf(fs[u], zt[u] - c, c);
            P *= (1.f - fs[u]);
        }
    }
    Pc_buf[idx] = P;
    Cc_buf[idx] = c;
}

// ---------------- scan phase 2: prefix + re-scan, write h (fp16) + final c ----------------
__global__ __launch_bounds__(256)
void scan_phase2_kernel(const __half* __restrict__ g, __half* __restrict__ H,
                        float* __restrict__ out, int layer, int write_h) {
    int idx = blockIdx.x * 256 + threadIdx.x;
    if (idx >= NCH * B_DIM * H_DIM) return;
    int j = idx % H_DIM;
    int b = (idx / H_DIM) % B_DIM;
    int ch = idx / (H_DIM * B_DIM);

    float c = 0.f;
    for (int i = 0; i < ch; i++) {
        size_t o = ((size_t)i * B_DIM + b) * H_DIM + j;
        c = Cc_buf[o] + Pc_buf[o] * c;
    }

    const __half* gp = g + (size_t)b * N_OUT + j;
    int t0b = ch * TC;
    for (int t0 = t0b; t0 < t0b + TC; t0 += 4) {
        float zt[4], fs[4], os[4];
#pragma unroll
        for (int u = 0; u < 4; u++) {
            size_t base = (size_t)(t0 + u) * B_DIM * N_OUT;
            zt[u] = __half2float(gp[base]);
            fs[u] = __half2float(gp[base + H_DIM]);
            os[u] = __half2float(gp[base + 2 * H_DIM]);
        }
#pragma unroll
        for (int u = 0; u < 4; u++) {
            c = fmaf(fs[u], zt[u] - c, c);
            if (write_h)
                H[(size_t)((t0 + u) * B_DIM + b) * KPAD + j] = __float2half(os[u] * c);
        }
    }
    if (ch == NCH - 1)
        out[(size_t)b * (L_DIM * H_DIM) + (size_t)layer * H_DIM + j] = c;
}

// ---------------- launch ----------------
extern "C" void kernel_launch(void* const* d_in, const int* in_sizes, int n_in,
                              void* d_out, int out_size) {
    const float* sent = (const float*)d_in[0];
    const float* W0 = (const float*)d_in[2];
    const float* b0 = (const float*)d_in[3];
    const float* W1 = (const float*)d_in[4];
    const float* b1 = (const float*)d_in[5];
    const float* W2 = (const float*)d_in[6];
    const float* b2 = (const float*)d_in[7];
    float* out = (float*)d_out;

    __half* g;  cudaGetSymbolAddress((void**)&g, g_buf);
    __half *a0, *a12, *w0h, *w0l, *w1h, *w1l, *w2h, *w2l;
    cudaGetSymbolAddress((void**)&a0, A0_buf);
    cudaGetSymbolAddress((void**)&a12, A12_buf);
    cudaGetSymbolAddress((void**)&w0h, W0h_buf); cudaGetSymbolAddress((void**)&w0l, W0l_buf);
    cudaGetSymbolAddress((void**)&w1h, W1h_buf); cudaGetSymbolAddress((void**)&w1l, W1l_buf);
    cudaGetSymbolAddress((void**)&w2h, W2h_buf); cudaGetSymbolAddress((void**)&w2l, W2l_buf);

    cudaFuncSetAttribute(qrnn_gemm_kernel, cudaFuncAttributeMaxDynamicSharedMemorySize,
                         STAGES * STAGE_BYTES);

    // zero A12 so its K-padding columns (800..831) stay 0 across layers
    cudaMemsetAsync(a12, 0, (size_t)M_DIM * KPAD * sizeof(__half), 0);

    dim3 wblk(32, 8);
    dim3 wgrid0(N_PADROWS / 32, KPAD0 / 32);
    dim3 wgrid12(N_PADROWS / 32, KPAD / 32);
    conv_w_kernel<<<wgrid0, wblk>>>(W0, w0h, w0l, E_DIM, KPAD0);
    conv_w_kernel<<<wgrid12, wblk>>>(W1, w1h, w1l, H_DIM, KPAD);
    conv_w_kernel<<<wgrid12, wblk>>>(W2, w2h, w2l, H_DIM, KPAD);

    {
        size_t n = (size_t)M_DIM * KPAD0;
        conv_sent_kernel<<<(unsigned)((n + 255) / 256), 256>>>(sent);
    }

    dim3 ggrid(N_PADROWS / BN, M_DIM / BM);   // (19, 256)
    size_t smem = STAGES * STAGE_BYTES;
    int scan_total = NCH * B_DIM * H_DIM;
    int scan_blocks = (scan_total + 255) / 256;

    qrnn_gemm_kernel<<<ggrid, 256, smem>>>(a0, w0h, w0l, KPAD0, KPAD0 / BK, b0, g);
    scan_phase1_kernel<<<scan_blocks, 256>>>(g);
    scan_phase2_kernel<<<scan_blocks, 256>>>(g, a12, out, 0, 1);

    qrnn_gemm_kernel<<<ggrid, 256, smem>>>(a12, w1h, w1l, KPAD, KPAD / BK, b1, g);
    scan_phase1_kernel<<<scan_blocks, 256>>>(g);
    scan_phase2_kernel<<<scan_blocks, 256>>>(g, a12, out, 1, 1);

    qrnn_gemm_kernel<<<ggrid, 256, smem>>>(a12, w2h, w2l, KPAD, KPAD / BK, b2, g);
    scan_phase1_kernel<<<scan_blocks, 256>>>(g);
    scan_phase2_kernel<<<scan_blocks, 256>>>(g, a12, out, 2, 0);
}

// round 7
// speedup vs baseline: 2.7790x; 1.4593x over previous
#include <cuda_runtime.h>
#include <cuda_fp16.h>
#include <cstdint>
#include <math.h>

// ---------------- problem constants ----------------
#define T_DIM 512
#define B_DIM 64
#define E_DIM 300
#define H_DIM 800
#define L_DIM 3
#define M_DIM (T_DIM * B_DIM)   // 32768
#define N_OUT 2400              // 3*H
#define N_PADROWS 2432          // N padded to mult of 128
#define KPAD0 320               // 300 -> mult of 32
#define KPAD  832               // 800 -> mult of 32

// scan chunking
#define NCH 8
#define TC  (T_DIM / NCH)       // 64

// GEMM tiling
#define BM 128
#define BN 128
#define BK 32
#define STAGES 3
#define STAGE_BYTES 16384       // A 8K | B 8K
#define A_OFF  0
#define B_OFF  8192

// ---------------- static scratch ----------------
__device__ __half g_buf[(size_t)M_DIM * N_OUT];           // post-activation z|f|o (fp16)
__device__ __half A0_buf[(size_t)M_DIM * KPAD0];          // layer0 A operand
__device__ __half A12_buf[(size_t)M_DIM * KPAD];          // layers 1/2 A operand (h)
__device__ __half W0_buf[(size_t)N_PADROWS * KPAD0];
__device__ __half W1_buf[(size_t)N_PADROWS * KPAD];
__device__ __half W2_buf[(size_t)N_PADROWS * KPAD];
__device__ float Pc_buf[(size_t)NCH * B_DIM * H_DIM];     // per-chunk product of (1-f)
__device__ float Cc_buf[(size_t)NCH * B_DIM * H_DIM];     // per-chunk local final c

// ---------------- helpers ----------------
__device__ __forceinline__ uint32_t smem_u32(const void* p) {
    uint32_t a;
    asm("{ .reg .u64 t; cvta.to.shared.u64 t, %1; cvt.u32.u64 %0, t; }" : "=r"(a) : "l"(p));
    return a;
}
__device__ __forceinline__ void cp16(uint32_t dst, const void* src) {
    asm volatile("cp.async.cg.shared.global [%0], [%1], 16;" :: "r"(dst), "l"(src) : "memory");
}
__device__ __forceinline__ void cp_commit() {
    asm volatile("cp.async.commit_group;" ::: "memory");
}
template <int N> __device__ __forceinline__ void cp_wait() {
    asm volatile("cp.async.wait_group %0;" :: "n"(N) : "memory");
}
__device__ __forceinline__ void ldsm4(uint32_t& r0, uint32_t& r1, uint32_t& r2, uint32_t& r3,
                                      uint32_t addr) {
    asm volatile("ldmatrix.sync.aligned.m8n8.x4.shared.b16 {%0,%1,%2,%3}, [%4];"
                 : "=r"(r0), "=r"(r1), "=r"(r2), "=r"(r3) : "r"(addr));
}
__device__ __forceinline__ void mma_f16(float* c, const uint32_t* a, const uint32_t* b) {
    asm volatile(
        "mma.sync.aligned.m16n8k16.row.col.f32.f16.f16.f32 "
        "{%0,%1,%2,%3}, {%4,%5,%6,%7}, {%8,%9}, {%0,%1,%2,%3};"
        : "+f"(c[0]), "+f"(c[1]), "+f"(c[2]), "+f"(c[3])
        : "r"(a[0]), "r"(a[1]), "r"(a[2]), "r"(a[3]), "r"(b[0]), "r"(b[1]));
}
__device__ __forceinline__ float sigmoidf_(float x) { return 1.f / (1.f + __expf(-x)); }
__device__ __forceinline__ float tanhf_(float x)    { return 1.f - 2.f / (__expf(2.f * x) + 1.f); }

// ---------------- weight transpose fp16: W[K,N] -> Wt[Np,Kp] ----------------
__global__ void conv_w_kernel(const float* __restrict__ W,
                              __half* __restrict__ Tw, int K, int Kp) {
    __shared__ float tile[32][33];
    int kb = blockIdx.y * 32, nb = blockIdx.x * 32;
    for (int r = threadIdx.y; r < 32; r += 8) {
        int k = kb + r, n = nb + threadIdx.x;
        tile[r][threadIdx.x] = (k < K && n < N_OUT) ? W[(size_t)k * N_OUT + n] : 0.f;
    }
    __syncthreads();
    for (int r = threadIdx.y; r < 32; r += 8) {
        int n = nb + r, k = kb + threadIdx.x;
        Tw[(size_t)n * Kp + k] = __float2half(tile[threadIdx.x][r]);
    }
}

// ---------------- sent fp32 -> fp16 (padded K) ----------------
__global__ void conv_sent_kernel(const float* __restrict__ x) {
    size_t i = (size_t)blockIdx.x * 256 + threadIdx.x;
    if (i >= (size_t)M_DIM * KPAD0) return;
    size_t row = i / KPAD0;
    int j = (int)(i % KPAD0);
    A0_buf[i] = __float2half((j < E_DIM) ? x[row * E_DIM + j] : 0.f);
}

// ---------------- fp16 HMMA GEMM (128x128 tile) with fused bias + activation ----------
// g[m,n] = act( sum_k A[m,k]*W[n,k] + bias[n] ), stored fp16
__global__ __launch_bounds__(256, 2)
void qrnn_gemm_kernel(const __half* __restrict__ A, const __half* __restrict__ B,
                      int ldk, int nc,
                      const float* __restrict__ bias, __half* __restrict__ C) {
    extern __shared__ char smem[];
    const uint32_t sbase = smem_u32(smem);

    const int tid = threadIdx.x;
    const int lane = tid & 31;
    const int wid = tid >> 5;
    const int wm = wid >> 2;          // 0..1 -> 64-row slabs
    const int wn = wid & 3;           // 0..3 -> 32-col slabs
    const int am0 = blockIdx.y * BM;
    const int bn0 = blockIdx.x * BN;

    auto load_stage = [&](int kc, int st) {
        const size_t kof = (size_t)kc * BK;
        uint32_t sb = sbase + st * STAGE_BYTES;
#pragma unroll
        for (int i = 0; i < 2; i++) {
            int id = tid + i * 256;        // 0..511
            int row = id >> 2, c = id & 3;
            int sc = c ^ ((row >> 1) & 3);
            uint32_t soff = row * 64 + sc * 16;
            cp16(sb + A_OFF + soff, A + (size_t)(am0 + row) * ldk + kof + (size_t)c * 8);
            cp16(sb + B_OFF + soff, B + (size_t)(bn0 + row) * ldk + kof + (size_t)c * 8);
        }
    };

    float acc[4][4][4];
#pragma unroll
    for (int i = 0; i < 4; i++)
#pragma unroll
        for (int j = 0; j < 4; j++)
#pragma unroll
            for (int q = 0; q < 4; q++) acc[i][j][q] = 0.f;

    load_stage(0, 0); cp_commit();
    if (nc > 1) { load_stage(1, 1); cp_commit(); }

    const int lr = lane & 15;
    const int lc = lane >> 4;

    for (int kc = 0; kc < nc; kc++) {
        if (kc + 1 < nc) cp_wait<1>(); else cp_wait<0>();
        __syncthreads();
        if (kc + 2 < nc) { load_stage(kc + 2, (kc + 2) % STAGES); cp_commit(); }

        uint32_t sb = sbase + (kc % STAGES) * STAGE_BYTES;
#pragma unroll
        for (int kk = 0; kk < 2; kk++) {
            uint32_t bh[4][2];
#pragma unroll
            for (int p = 0; p < 2; p++) {
                int rowb = wn * 32 + p * 16 + lr;
                uint32_t off = rowb * 64 + (((kk * 2 + lc) ^ ((rowb >> 1) & 3)) * 16);
                uint32_t r0, r1, r2, r3;
                ldsm4(r0, r1, r2, r3, sb + B_OFF + off);
                bh[2 * p][0] = r0; bh[2 * p + 1][0] = r1;
                bh[2 * p][1] = r2; bh[2 * p + 1][1] = r3;
            }
#pragma unroll
            for (int mt = 0; mt < 4; mt++) {
                int rowa = wm * 64 + mt * 16 + lr;
                uint32_t off = rowa * 64 + (((kk * 2 + lc) ^ ((rowa >> 1) & 3)) * 16);
                uint32_t a[4];
                ldsm4(a[0], a[1], a[2], a[3], sb + A_OFF + off);
#pragma unroll
                for (int ng = 0; ng < 4; ng++)
                    mma_f16(acc[mt][ng], a, bh[ng]);
            }
        }
        __syncthreads();
    }

    // ---- epilogue: bias + activation, half2 stores ----
    const int tg = lane >> 2;
    const int tq = lane & 3;
#pragma unroll
    for (int ng = 0; ng < 4; ng++) {
        int colb = bn0 + wn * 32 + ng * 8;
        if (colb >= N_OUT) continue;
        int col = colb + tq * 2;
        float2 bv = *reinterpret_cast<const float2*>(&bias[col]);
        bool is_t = colb < H_DIM;
#pragma unroll
        for (int mt = 0; mt < 4; mt++) {
            int r0 = am0 + wm * 64 + mt * 16 + tg;
            float x0 = acc[mt][ng][0] + bv.x;
            float x1 = acc[mt][ng][1] + bv.y;
            float x2 = acc[mt][ng][2] + bv.x;
            float x3 = acc[mt][ng][3] + bv.y;
            float v0 = is_t ? tanhf_(x0) : sigmoidf_(x0);
            float v1 = is_t ? tanhf_(x1) : sigmoidf_(x1);
            float v2 = is_t ? tanhf_(x2) : sigmoidf_(x2);
            float v3 = is_t ? tanhf_(x3) : sigmoidf_(x3);
            *reinterpret_cast<__half2*>(&C[(size_t)r0 * N_OUT + col]) =
                __floats2half2_rn(v0, v1);
            *reinterpret_cast<__half2*>(&C[(size_t)(r0 + 8) * N_OUT + col]) =
                __floats2half2_rn(v2, v3);
        }
    }
}

// ---------------- scan phase 1: per-chunk (prod(1-f), local c) ----------------
__global__ __launch_bounds__(256)
void scan_phase1_kernel(const __half* __restrict__ g) {
    int idx = blockIdx.x * 256 + threadIdx.x;
    if (idx >= NCH * B_DIM * H_DIM) return;
    int j = idx % H_DIM;
    int b = (idx / H_DIM) % B_DIM;
    int ch = idx / (H_DIM * B_DIM);

    const __half* gp = g + (size_t)b * N_OUT + j;
    float c = 0.f, P = 1.f;
    int t0b = ch * TC;
    for (int t0 = t0b; t0 < t0b + TC; t0 += 4) {
        float zt[4], fs[4];
#pragma unroll
        for (int u = 0; u < 4; u++) {
            size_t base = (size_t)(t0 + u) * B_DIM * N_OUT;
            zt[u] = __half2float(gp[base]);
            fs[u] = __half2float(gp[base + H_DIM]);
        }
#pragma unroll
        for (int u = 0; u < 4; u++) {
            c = fmaf(fs[u], zt[u] - c, c);
            P *= (1.f - fs[u]);
        }
    }
    Pc_buf[idx] = P;
    Cc_buf[idx] = c;
}

// ---------------- scan phase 2: prefix + re-scan, write h (fp16) + final c ----------------
__global__ __launch_bounds__(256)
void scan_phase2_kernel(const __half* __restrict__ g, __half* __restrict__ H,
                        float* __restrict__ out, int layer, int write_h) {
    int idx = blockIdx.x * 256 + threadIdx.x;
    if (idx >= NCH * B_DIM * H_DIM) return;
    int j = idx % H_DIM;
    int b = (idx / H_DIM) % B_DIM;
    int ch = idx / (H_DIM * B_DIM);

    float c = 0.f;
    for (int i = 0; i < ch; i++) {
        size_t o = ((size_t)i * B_DIM + b) * H_DIM + j;
        c = Cc_buf[o] + Pc_buf[o] * c;
    }

    const __half* gp = g + (size_t)b * N_OUT + j;
    int t0b = ch * TC;
    for (int t0 = t0b; t0 < t0b + TC; t0 += 4) {
        float zt[4], fs[4], os[4];
#pragma unroll
        for (int u = 0; u < 4; u++) {
            size_t base = (size_t)(t0 + u) * B_DIM * N_OUT;
            zt[u] = __half2float(gp[base]);
            fs[u] = __half2float(gp[base + H_DIM]);
            os[u] = __half2float(gp[base + 2 * H_DIM]);
        }
#pragma unroll
        for (int u = 0; u < 4; u++) {
            c = fmaf(fs[u], zt[u] - c, c);
            if (write_h)
                H[(size_t)((t0 + u) * B_DIM + b) * KPAD + j] = __float2half(os[u] * c);
        }
    }
    if (ch == NCH - 1)
        out[(size_t)b * (L_DIM * H_DIM) + (size_t)layer * H_DIM + j] = c;
}

// ---------------- launch ----------------
extern "C" void kernel_launch(void* const* d_in, const int* in_sizes, int n_in,
                              void* d_out, int out_size) {
    const float* sent = (const float*)d_in[0];
    const float* W0 = (const float*)d_in[2];
    const float* b0 = (const float*)d_in[3];
    const float* W1 = (const float*)d_in[4];
    const float* b1 = (const float*)d_in[5];
    const float* W2 = (const float*)d_in[6];
    const float* b2 = (const float*)d_in[7];
    float* out = (float*)d_out;

    __half* g;  cudaGetSymbolAddress((void**)&g, g_buf);
    __half *a0, *a12, *w0, *w1, *w2;
    cudaGetSymbolAddress((void**)&a0, A0_buf);
    cudaGetSymbolAddress((void**)&a12, A12_buf);
    cudaGetSymbolAddress((void**)&w0, W0_buf);
    cudaGetSymbolAddress((void**)&w1, W1_buf);
    cudaGetSymbolAddress((void**)&w2, W2_buf);

    cudaFuncSetAttribute(qrnn_gemm_kernel, cudaFuncAttributeMaxDynamicSharedMemorySize,
                         STAGES * STAGE_BYTES);

    // zero A12 so its K-padding columns (800..831) stay 0 across layers
    cudaMemsetAsync(a12, 0, (size_t)M_DIM * KPAD * sizeof(__half), 0);

    dim3 wblk(32, 8);
    dim3 wgrid0(N_PADROWS / 32, KPAD0 / 32);
    dim3 wgrid12(N_PADROWS / 32, KPAD / 32);
    conv_w_kernel<<<wgrid0, wblk>>>(W0, w0, E_DIM, KPAD0);
    conv_w_kernel<<<wgrid12, wblk>>>(W1, w1, H_DIM, KPAD);
    conv_w_kernel<<<wgrid12, wblk>>>(W2, w2, H_DIM, KPAD);

    {
        size_t n = (size_t)M_DIM * KPAD0;
        conv_sent_kernel<<<(unsigned)((n + 255) / 256), 256>>>(sent);
    }

    dim3 ggrid(N_PADROWS / BN, M_DIM / BM);   // (19, 256)
    size_t smem = STAGES * STAGE_BYTES;
    int scan_total = NCH * B_DIM * H_DIM;
    int scan_blocks = (scan_total + 255) / 256;

    qrnn_gemm_kernel<<<ggrid, 256, smem>>>(a0, w0, KPAD0, KPAD0 / BK, b0, g);
    scan_phase1_kernel<<<scan_blocks, 256>>>(g);
    scan_phase2_kernel<<<scan_blocks, 256>>>(g, a12, out, 0, 1);

    qrnn_gemm_kernel<<<ggrid, 256, smem>>>(a12, w1, KPAD, KPAD / BK, b1, g);
    scan_phase1_kernel<<<scan_blocks, 256>>>(g);
    scan_phase2_kernel<<<scan_blocks, 256>>>(g, a12, out, 1, 1);

    qrnn_gemm_kernel<<<ggrid, 256, smem>>>(a12, w2, KPAD, KPAD / BK, b2, g);
    scan_phase1_kernel<<<scan_blocks, 256>>>(g);
    scan_phase2_kernel<<<scan_blocks, 256>>>(g, a12, out, 2, 0);
}

// round 8
// speedup vs baseline: 3.0618x; 1.1018x over previous
#include <cuda_runtime.h>
#include <cuda_fp16.h>
#include <cstdint>
#include <math.h>

// ---------------- problem constants ----------------
#define T_DIM 512
#define B_DIM 64
#define E_DIM 300
#define H_DIM 800
#define L_DIM 3
#define M_DIM (T_DIM * B_DIM)   // 32768
#define N_OUT 2400              // 3*H
#define N_PADROWS 2432          // N padded to mult of 128
#define KPAD0 320               // 300 -> mult of 64
#define KPAD  832               // 800 -> mult of 64

// scan chunking
#define NCH 16
#define TC  (T_DIM / NCH)       // 32

// GEMM tiling
#define BM 128
#define BN 128
#define BK 64
#define STAGES 3
#define STAGE_BYTES 32768       // A 16K | B 16K
#define A_OFF  0
#define B_OFF  16384

// ---------------- static scratch ----------------
__device__ __half g_buf[(size_t)M_DIM * N_OUT];           // post-activation z|f|o (fp16)
__device__ __half A0_buf[(size_t)M_DIM * KPAD0];          // layer0 A operand
__device__ __half A12_buf[(size_t)M_DIM * KPAD];          // layers 1/2 A operand (h); padding stays 0
__device__ __half W0_buf[(size_t)N_PADROWS * KPAD0];
__device__ __half W1_buf[(size_t)N_PADROWS * KPAD];
__device__ __half W2_buf[(size_t)N_PADROWS * KPAD];
__device__ float Pc_buf[(size_t)NCH * B_DIM * H_DIM];     // per-chunk product of (1-f)
__device__ float Cc_buf[(size_t)NCH * B_DIM * H_DIM];     // per-chunk local final c

// ---------------- helpers ----------------
__device__ __forceinline__ uint32_t smem_u32(const void* p) {
    uint32_t a;
    asm("{ .reg .u64 t; cvta.to.shared.u64 t, %1; cvt.u32.u64 %0, t; }" : "=r"(a) : "l"(p));
    return a;
}
__device__ __forceinline__ void cp16(uint32_t dst, const void* src) {
    asm volatile("cp.async.cg.shared.global [%0], [%1], 16;" :: "r"(dst), "l"(src) : "memory");
}
__device__ __forceinline__ void cp_commit() {
    asm volatile("cp.async.commit_group;" ::: "memory");
}
template <int N> __device__ __forceinline__ void cp_wait() {
    asm volatile("cp.async.wait_group %0;" :: "n"(N) : "memory");
}
__device__ __forceinline__ void ldsm4(uint32_t& r0, uint32_t& r1, uint32_t& r2, uint32_t& r3,
                                      uint32_t addr) {
    asm volatile("ldmatrix.sync.aligned.m8n8.x4.shared.b16 {%0,%1,%2,%3}, [%4];"
                 : "=r"(r0), "=r"(r1), "=r"(r2), "=r"(r3) : "r"(addr));
}
__device__ __forceinline__ void mma_f16(float* c, const uint32_t* a, const uint32_t* b) {
    asm volatile(
        "mma.sync.aligned.m16n8k16.row.col.f32.f16.f16.f32 "
        "{%0,%1,%2,%3}, {%4,%5,%6,%7}, {%8,%9}, {%0,%1,%2,%3};"
        : "+f"(c[0]), "+f"(c[1]), "+f"(c[2]), "+f"(c[3])
        : "r"(a[0]), "r"(a[1]), "r"(a[2]), "r"(a[3]), "r"(b[0]), "r"(b[1]));
}
__device__ __forceinline__ float sigmoidf_(float x) { return 1.f / (1.f + __expf(-x)); }
__device__ __forceinline__ float tanhf_(float x)    { return 1.f - 2.f / (__expf(2.f * x) + 1.f); }

// ---------------- weight transpose fp16: W[K,N] -> Wt[Np,Kp] ----------------
__global__ void conv_w_kernel(const float* __restrict__ W,
                              __half* __restrict__ Tw, int K, int Kp) {
    __shared__ float tile[32][33];
    int kb = blockIdx.y * 32, nb = blockIdx.x * 32;
    for (int r = threadIdx.y; r < 32; r += 8) {
        int k = kb + r, n = nb + threadIdx.x;
        tile[r][threadIdx.x] = (k < K && n < N_OUT) ? W[(size_t)k * N_OUT + n] : 0.f;
    }
    __syncthreads();
    for (int r = threadIdx.y; r < 32; r += 8) {
        int n = nb + r, k = kb + threadIdx.x;
        Tw[(size_t)n * Kp + k] = __float2half(tile[threadIdx.x][r]);
    }
}

// ---------------- sent fp32 -> fp16 (padded K) ----------------
__global__ void conv_sent_kernel(const float* __restrict__ x) {
    size_t i = (size_t)blockIdx.x * 256 + threadIdx.x;
    if (i >= (size_t)M_DIM * KPAD0) return;
    size_t row = i / KPAD0;
    int j = (int)(i % KPAD0);
    A0_buf[i] = __float2half((j < E_DIM) ? x[row * E_DIM + j] : 0.f);
}

// ---------------- fp16 HMMA GEMM (128x128 tile, BK=64) with fused bias + activation ----
// g[m,n] = act( sum_k A[m,k]*W[n,k] + bias[n] ), stored fp16
__global__ __launch_bounds__(256, 2)
void qrnn_gemm_kernel(const __half* __restrict__ A, const __half* __restrict__ B,
                      int ldk, int nc,
                      const float* __restrict__ bias, __half* __restrict__ C) {
    extern __shared__ char smem[];
    const uint32_t sbase = smem_u32(smem);

    const int tid = threadIdx.x;
    const int lane = tid & 31;
    const int wid = tid >> 5;
    const int wm = wid >> 2;          // 0..1 -> 64-row slabs
    const int wn = wid & 3;           // 0..3 -> 32-col slabs
    const int am0 = blockIdx.y * BM;
    const int bn0 = blockIdx.x * BN;

    // stage: A[128][64] fp16 row-pitch 128B, full SW128 swizzle; B same
    auto load_stage = [&](int kc, int st) {
        const size_t kof = (size_t)kc * BK;
        uint32_t sb = sbase + st * STAGE_BYTES;
#pragma unroll
        for (int i = 0; i < 4; i++) {
            int id = tid + i * 256;            // 0..1023
            int row = id >> 3, c = id & 7;
            int sc = c ^ (row & 7);
            uint32_t soff = row * 128 + sc * 16;
            cp16(sb + A_OFF + soff, A + (size_t)(am0 + row) * ldk + kof + (size_t)c * 8);
            cp16(sb + B_OFF + soff, B + (size_t)(bn0 + row) * ldk + kof + (size_t)c * 8);
        }
    };

    float acc[4][4][4];
#pragma unroll
    for (int i = 0; i < 4; i++)
#pragma unroll
        for (int j = 0; j < 4; j++)
#pragma unroll
            for (int q = 0; q < 4; q++) acc[i][j][q] = 0.f;

    load_stage(0, 0); cp_commit();
    if (nc > 1) { load_stage(1, 1); cp_commit(); }

    const int lr = lane & 15;
    const int lc = lane >> 4;

    for (int kc = 0; kc < nc; kc++) {
        if (kc + 1 < nc) cp_wait<1>(); else cp_wait<0>();
        __syncthreads();
        if (kc + 2 < nc) { load_stage(kc + 2, (kc + 2) % STAGES); cp_commit(); }

        uint32_t sb = sbase + (kc % STAGES) * STAGE_BYTES;
#pragma unroll
        for (int kk = 0; kk < 4; kk++) {       // 4 k16 groups in BK=64
            uint32_t bh[4][2];
#pragma unroll
            for (int p = 0; p < 2; p++) {
                int rowb = wn * 32 + p * 16 + lr;
                uint32_t off = rowb * 128 + (((kk * 2 + lc) ^ (rowb & 7)) * 16);
                uint32_t r0, r1, r2, r3;
                ldsm4(r0, r1, r2, r3, sb + B_OFF + off);
                bh[2 * p][0] = r0; bh[2 * p + 1][0] = r1;
                bh[2 * p][1] = r2; bh[2 * p + 1][1] = r3;
            }
#pragma unroll
            for (int mt = 0; mt < 4; mt++) {
                int rowa = wm * 64 + mt * 16 + lr;
                uint32_t off = rowa * 128 + (((kk * 2 + lc) ^ (rowa & 7)) * 16);
                uint32_t a[4];
                ldsm4(a[0], a[1], a[2], a[3], sb + A_OFF + off);
#pragma unroll
                for (int ng = 0; ng < 4; ng++)
                    mma_f16(acc[mt][ng], a, bh[ng]);
            }
        }
        __syncthreads();
    }

    // ---- epilogue: bias + activation, half2 stores ----
    const int tg = lane >> 2;
    const int tq = lane & 3;
#pragma unroll
    for (int ng = 0; ng < 4; ng++) {
        int colb = bn0 + wn * 32 + ng * 8;
        if (colb >= N_OUT) continue;
        int col = colb + tq * 2;
        float2 bv = *reinterpret_cast<const float2*>(&bias[col]);
        bool is_t = colb < H_DIM;
#pragma unroll
        for (int mt = 0; mt < 4; mt++) {
            int r0 = am0 + wm * 64 + mt * 16 + tg;
            float x0 = acc[mt][ng][0] + bv.x;
            float x1 = acc[mt][ng][1] + bv.y;
            float x2 = acc[mt][ng][2] + bv.x;
            float x3 = acc[mt][ng][3] + bv.y;
            float v0 = is_t ? tanhf_(x0) : sigmoidf_(x0);
            float v1 = is_t ? tanhf_(x1) : sigmoidf_(x1);
            float v2 = is_t ? tanhf_(x2) : sigmoidf_(x2);
            float v3 = is_t ? tanhf_(x3) : sigmoidf_(x3);
            *reinterpret_cast<__half2*>(&C[(size_t)r0 * N_OUT + col]) =
                __floats2half2_rn(v0, v1);
            *reinterpret_cast<__half2*>(&C[(size_t)(r0 + 8) * N_OUT + col]) =
                __floats2half2_rn(v2, v3);
        }
    }
}

// ---------------- scan phase 1: per-chunk (prod(1-f), local c) ----------------
__global__ __launch_bounds__(256)
void scan_phase1_kernel(const __half* __restrict__ g) {
    int idx = blockIdx.x * 256 + threadIdx.x;
    if (idx >= NCH * B_DIM * H_DIM) return;
    int j = idx % H_DIM;
    int b = (idx / H_DIM) % B_DIM;
    int ch = idx / (H_DIM * B_DIM);

    const __half* gp = g + (size_t)b * N_OUT + j;
    float c = 0.f, P = 1.f;
    int t0b = ch * TC;
    for (int t0 = t0b; t0 < t0b + TC; t0 += 4) {
        float zt[4], fs[4];
#pragma unroll
        for (int u = 0; u < 4; u++) {
            size_t base = (size_t)(t0 + u) * B_DIM * N_OUT;
            zt[u] = __half2float(gp[base]);
            fs[u] = __half2float(gp[base + H_DIM]);
        }
#pragma unroll
        for (int u = 0; u < 4; u++) {
            c = fmaf(fs[u], zt[u] - c, c);
            P *= (1.f - fs[u]);
        }
    }
    Pc_buf[idx] = P;
    Cc_buf[idx] = c;
}

// ---------------- scan phase 2: prefix + re-scan, write h (fp16) + final c ----------------
__global__ __launch_bounds__(256)
void scan_phase2_kernel(const __half* __restrict__ g, __half* __restrict__ H,
                        float* __restrict__ out, int layer, int write_h) {
    int idx = blockIdx.x * 256 + threadIdx.x;
    if (idx >= NCH * B_DIM * H_DIM) return;
    int j = idx % H_DIM;
    int b = (idx / H_DIM) % B_DIM;
    int ch = idx / (H_DIM * B_DIM);

    float c = 0.f;
    for (int i = 0; i < ch; i++) {
        size_t o = ((size_t)i * B_DIM + b) * H_DIM + j;
        c = Cc_buf[o] + Pc_buf[o] * c;
    }

    const __half* gp = g + (size_t)b * N_OUT + j;
    int t0b = ch * TC;
    for (int t0 = t0b; t0 < t0b + TC; t0 += 4) {
        float zt[4], fs[4], os[4];
#pragma unroll
        for (int u = 0; u < 4; u++) {
            size_t base = (size_t)(t0 + u) * B_DIM * N_OUT;
            zt[u] = __half2float(gp[base]);
            fs[u] = __half2float(gp[base + H_DIM]);
            os[u] = __half2float(gp[base + 2 * H_DIM]);
        }
#pragma unroll
        for (int u = 0; u < 4; u++) {
            c = fmaf(fs[u], zt[u] - c, c);
            if (write_h)
                H[(size_t)((t0 + u) * B_DIM + b) * KPAD + j] = __float2half(os[u] * c);
        }
    }
    if (ch == NCH - 1)
        out[(size_t)b * (L_DIM * H_DIM) + (size_t)layer * H_DIM + j] = c;
}

// ---------------- launch ----------------
extern "C" void kernel_launch(void* const* d_in, const int* in_sizes, int n_in,
                              void* d_out, int out_size) {
    const float* sent = (const float*)d_in[0];
    const float* W0 = (const float*)d_in[2];
    const float* b0 = (const float*)d_in[3];
    const float* W1 = (const float*)d_in[4];
    const float* b1 = (const float*)d_in[5];
    const float* W2 = (const float*)d_in[6];
    const float* b2 = (const float*)d_in[7];
    float* out = (float*)d_out;

    __half* g;  cudaGetSymbolAddress((void**)&g, g_buf);
    __half *a0, *a12, *w0, *w1, *w2;
    cudaGetSymbolAddress((void**)&a0, A0_buf);
    cudaGetSymbolAddress((void**)&a12, A12_buf);
    cudaGetSymbolAddress((void**)&w0, W0_buf);
    cudaGetSymbolAddress((void**)&w1, W1_buf);
    cudaGetSymbolAddress((void**)&w2, W2_buf);

    cudaFuncSetAttribute(qrnn_gemm_kernel, cudaFuncAttributeMaxDynamicSharedMemorySize,
                         STAGES * STAGE_BYTES);

    // NOTE: A12_buf padding columns (800..831) are never written; device globals are
    // zero-initialized, so no memset is needed.

    dim3 wblk(32, 8);
    dim3 wgrid0(N_PADROWS / 32, KPAD0 / 32);
    dim3 wgrid12(N_PADROWS / 32, KPAD / 32);
    conv_w_kernel<<<wgrid0, wblk>>>(W0, w0, E_DIM, KPAD0);
    conv_w_kernel<<<wgrid12, wblk>>>(W1, w1, H_DIM, KPAD);
    conv_w_kernel<<<wgrid12, wblk>>>(W2, w2, H_DIM, KPAD);

    {
        size_t n = (size_t)M_DIM * KPAD0;
        conv_sent_kernel<<<(unsigned)((n + 255) / 256), 256>>>(sent);
    }

    dim3 ggrid(N_PADROWS / BN, M_DIM / BM);   // (19, 256)
    size_t smem = STAGES * STAGE_BYTES;
    int scan_total = NCH * B_DIM * H_DIM;
    int scan_blocks = (scan_total + 255) / 256;

    qrnn_gemm_kernel<<<ggrid, 256, smem>>>(a0, w0, KPAD0, KPAD0 / BK, b0, g);
    scan_phase1_kernel<<<scan_blocks, 256>>>(g);
    scan_phase2_kernel<<<scan_blocks, 256>>>(g, a12, out, 0, 1);

    qrnn_gemm_kernel<<<ggrid, 256, smem>>>(a12, w1, KPAD, KPAD / BK, b1, g);
    scan_phase1_kernel<<<scan_blocks, 256>>>(g);
    scan_phase2_kernel<<<scan_blocks, 256>>>(g, a12, out, 1, 1);

    qrnn_gemm_kernel<<<ggrid, 256, smem>>>(a12, w2, KPAD, KPAD / BK, b2, g);
    scan_phase1_kernel<<<scan_blocks, 256>>>(g);
    scan_phase2_kernel<<<scan_blocks, 256>>>(g, a12, out, 2, 0);
}

// round 9
// speedup vs baseline: 3.1469x; 1.0278x over previous
#include <cuda_runtime.h>
#include <cuda_fp16.h>
#include <cstdint>
#include <math.h>

// ---------------- problem constants ----------------
#define T_DIM 512
#define B_DIM 64
#define E_DIM 300
#define H_DIM 800
#define L_DIM 3
#define M_DIM (T_DIM * B_DIM)   // 32768
#define N_OUT 2400              // 3*H
#define N_PADROWS 2432          // N padded to mult of 128
#define KPAD0 320               // 300 -> mult of 64
#define KPAD  832               // 800 -> mult of 64

// scan chunking
#define NCH 16
#define TC  (T_DIM / NCH)       // 32

// GEMM tiling
#define BM 128
#define BN 128
#define BK 64
#define STAGES 3
#define STAGE_BYTES 32768       // A 16K | B 16K
#define A_OFF  0
#define B_OFF  16384

// ---------------- static scratch ----------------
__device__ __half g_buf[(size_t)M_DIM * N_OUT];           // post-activation z|f|o (fp16)
__device__ __half A0_buf[(size_t)M_DIM * KPAD0];          // layer0 A operand
__device__ __half A12_buf[(size_t)M_DIM * KPAD];          // layers 1/2 A operand (h); padding stays 0
__device__ __half W0_buf[(size_t)N_PADROWS * KPAD0];
__device__ __half W1_buf[(size_t)N_PADROWS * KPAD];
__device__ __half W2_buf[(size_t)N_PADROWS * KPAD];
__device__ float Pc_buf[(size_t)NCH * B_DIM * H_DIM];     // per-chunk product of (1-f)
__device__ float Cc_buf[(size_t)NCH * B_DIM * H_DIM];     // per-chunk local final c

// ---------------- helpers ----------------
__device__ __forceinline__ uint32_t smem_u32(const void* p) {
    uint32_t a;
    asm("{ .reg .u64 t; cvta.to.shared.u64 t, %1; cvt.u32.u64 %0, t; }" : "=r"(a) : "l"(p));
    return a;
}
__device__ __forceinline__ void cp16(uint32_t dst, const void* src) {
    asm volatile("cp.async.cg.shared.global [%0], [%1], 16;" :: "r"(dst), "l"(src) : "memory");
}
__device__ __forceinline__ void cp_commit() {
    asm volatile("cp.async.commit_group;" ::: "memory");
}
template <int N> __device__ __forceinline__ void cp_wait() {
    asm volatile("cp.async.wait_group %0;" :: "n"(N) : "memory");
}
__device__ __forceinline__ void ldsm4(uint32_t& r0, uint32_t& r1, uint32_t& r2, uint32_t& r3,
                                      uint32_t addr) {
    asm volatile("ldmatrix.sync.aligned.m8n8.x4.shared.b16 {%0,%1,%2,%3}, [%4];"
                 : "=r"(r0), "=r"(r1), "=r"(r2), "=r"(r3) : "r"(addr));
}
__device__ __forceinline__ void mma_f16(float* c, const uint32_t* a, const uint32_t* b) {
    asm volatile(
        "mma.sync.aligned.m16n8k16.row.col.f32.f16.f16.f32 "
        "{%0,%1,%2,%3}, {%4,%5,%6,%7}, {%8,%9}, {%0,%1,%2,%3};"
        : "+f"(c[0]), "+f"(c[1]), "+f"(c[2]), "+f"(c[3])
        : "r"(a[0]), "r"(a[1]), "r"(a[2]), "r"(a[3]), "r"(b[0]), "r"(b[1]));
}
__device__ __forceinline__ float sigmoidf_(float x) { return 1.f / (1.f + __expf(-x)); }
__device__ __forceinline__ float tanhf_(float x)    { return 1.f - 2.f / (__expf(2.f * x) + 1.f); }

// ---------------- weight transpose fp16: W[K,N] -> Wt[Np,Kp] ----------------
__global__ void conv_w_kernel(const float* __restrict__ W,
                              __half* __restrict__ Tw, int K, int Kp) {
    __shared__ float tile[32][33];
    int kb = blockIdx.y * 32, nb = blockIdx.x * 32;
    for (int r = threadIdx.y; r < 32; r += 8) {
        int k = kb + r, n = nb + threadIdx.x;
        tile[r][threadIdx.x] = (k < K && n < N_OUT) ? W[(size_t)k * N_OUT + n] : 0.f;
    }
    __syncthreads();
    for (int r = threadIdx.y; r < 32; r += 8) {
        int n = nb + r, k = kb + threadIdx.x;
        Tw[(size_t)n * Kp + k] = __float2half(tile[threadIdx.x][r]);
    }
}

// ---------------- sent fp32 -> fp16 (padded K), vectorized ----------------
// one thread = 4 consecutive j (float4 read, 2x half2 write); KPAD0/4 = 80 per row
__global__ void conv_sent_kernel(const float* __restrict__ x) {
    int i = blockIdx.x * 256 + threadIdx.x;
    if (i >= M_DIM * (KPAD0 / 4)) return;
    int row = i / (KPAD0 / 4);
    int j4 = (i % (KPAD0 / 4)) * 4;
    uint2 outv;
    if (j4 < E_DIM) {   // E_DIM=300 divisible by 4, so full vector is in-bounds
        float4 v = *reinterpret_cast<const float4*>(x + (size_t)row * E_DIM + j4);
        __half2 h0 = __floats2half2_rn(v.x, v.y);
        __half2 h1 = __floats2half2_rn(v.z, v.w);
        outv.x = *reinterpret_cast<uint32_t*>(&h0);
        outv.y = *reinterpret_cast<uint32_t*>(&h1);
    } else {
        outv.x = 0u; outv.y = 0u;
    }
    *reinterpret_cast<uint2*>(&A0_buf[(size_t)row * KPAD0 + j4]) = outv;
}

// ---------------- fp16 HMMA GEMM (128x128 tile, BK=64) with fused bias + activation ----
// g[m,n] = act( sum_k A[m,k]*W[n,k] + bias[n] ), stored fp16
__global__ __launch_bounds__(256, 2)
void qrnn_gemm_kernel(const __half* __restrict__ A, const __half* __restrict__ B,
                      int ldk, int nc,
                      const float* __restrict__ bias, __half* __restrict__ C) {
    extern __shared__ char smem[];
    const uint32_t sbase = smem_u32(smem);

    const int tid = threadIdx.x;
    const int lane = tid & 31;
    const int wid = tid >> 5;
    const int wm = wid >> 2;          // 0..1 -> 64-row slabs
    const int wn = wid & 3;           // 0..3 -> 32-col slabs
    const int am0 = blockIdx.y * BM;
    const int bn0 = blockIdx.x * BN;

    // stage: A[128][64] fp16 row-pitch 128B, full SW128 swizzle; B same
    auto load_stage = [&](int kc, int st) {
        const size_t kof = (size_t)kc * BK;
        uint32_t sb = sbase + st * STAGE_BYTES;
#pragma unroll
        for (int i = 0; i < 4; i++) {
            int id = tid + i * 256;            // 0..1023
            int row = id >> 3, c = id & 7;
            int sc = c ^ (row & 7);
            uint32_t soff = row * 128 + sc * 16;
            cp16(sb + A_OFF + soff, A + (size_t)(am0 + row) * ldk + kof + (size_t)c * 8);
            cp16(sb + B_OFF + soff, B + (size_t)(bn0 + row) * ldk + kof + (size_t)c * 8);
        }
    };

    float acc[4][4][4];
#pragma unroll
    for (int i = 0; i < 4; i++)
#pragma unroll
        for (int j = 0; j < 4; j++)
#pragma unroll
            for (int q = 0; q < 4; q++) acc[i][j][q] = 0.f;

    load_stage(0, 0); cp_commit();
    if (nc > 1) { load_stage(1, 1); cp_commit(); }

    const int lr = lane & 15;
    const int lc = lane >> 4;

    for (int kc = 0; kc < nc; kc++) {
        if (kc + 1 < nc) cp_wait<1>(); else cp_wait<0>();
        __syncthreads();   // also guarantees prior stage fully consumed by all warps
        if (kc + 2 < nc) { load_stage(kc + 2, (kc + 2) % STAGES); cp_commit(); }

        uint32_t sb = sbase + (kc % STAGES) * STAGE_BYTES;
#pragma unroll
        for (int kp = 0; kp < 2; kp++) {       // kk-pairs: 2x (4 B-ldsm, then 8 A-ldsm + 32 MMA)
            uint32_t breg[2][4][2];
#pragma unroll
            for (int kk2 = 0; kk2 < 2; kk2++) {
                int kk = kp * 2 + kk2;
#pragma unroll
                for (int p = 0; p < 2; p++) {
                    int rowb = wn * 32 + p * 16 + lr;
                    uint32_t off = rowb * 128 + (((kk * 2 + lc) ^ (rowb & 7)) * 16);
                    uint32_t r0, r1, r2, r3;
                    ldsm4(r0, r1, r2, r3, sb + B_OFF + off);
                    breg[kk2][2 * p][0] = r0; breg[kk2][2 * p + 1][0] = r1;
                    breg[kk2][2 * p][1] = r2; breg[kk2][2 * p + 1][1] = r3;
                }
            }
#pragma unroll
            for (int kk2 = 0; kk2 < 2; kk2++) {
                int kk = kp * 2 + kk2;
#pragma unroll
                for (int mt = 0; mt < 4; mt++) {
                    int rowa = wm * 64 + mt * 16 + lr;
                    uint32_t off = rowa * 128 + (((kk * 2 + lc) ^ (rowa & 7)) * 16);
                    uint32_t a[4];
                    ldsm4(a[0], a[1], a[2], a[3], sb + A_OFF + off);
#pragma unroll
                    for (int ng = 0; ng < 4; ng++)
                        mma_f16(acc[mt][ng], a, breg[kk2][ng]);
                }
            }
        }
        // no end-of-loop barrier: next iteration's top barrier provides the
        // consumption-complete guarantee before any overwrite of this stage
    }

    // ---- epilogue: bias + activation, half2 stores ----
    const int tg = lane >> 2;
    const int tq = lane & 3;
#pragma unroll
    for (int ng = 0; ng < 4; ng++) {
        int colb = bn0 + wn * 32 + ng * 8;
        if (colb >= N_OUT) continue;
        int col = colb + tq * 2;
        float2 bv = *reinterpret_cast<const float2*>(&bias[col]);
        bool is_t = colb < H_DIM;
#pragma unroll
        for (int mt = 0; mt < 4; mt++) {
            int r0 = am0 + wm * 64 + mt * 16 + tg;
            float x0 = acc[mt][ng][0] + bv.x;
            float x1 = acc[mt][ng][1] + bv.y;
            float x2 = acc[mt][ng][2] + bv.x;
            float x3 = acc[mt][ng][3] + bv.y;
            float v0 = is_t ? tanhf_(x0) : sigmoidf_(x0);
            float v1 = is_t ? tanhf_(x1) : sigmoidf_(x1);
            float v2 = is_t ? tanhf_(x2) : sigmoidf_(x2);
            float v3 = is_t ? tanhf_(x3) : sigmoidf_(x3);
            *reinterpret_cast<__half2*>(&C[(size_t)r0 * N_OUT + col]) =
                __floats2half2_rn(v0, v1);
            *reinterpret_cast<__half2*>(&C[(size_t)(r0 + 8) * N_OUT + col]) =
                __floats2half2_rn(v2, v3);
        }
    }
}

// ---------------- scan phase 1: per-chunk (prod(1-f), local c) ----------------
__global__ __launch_bounds__(256)
void scan_phase1_kernel(const __half* __restrict__ g) {
    int idx = blockIdx.x * 256 + threadIdx.x;
    if (idx >= NCH * B_DIM * H_DIM) return;
    int j = idx % H_DIM;
    int b = (idx / H_DIM) % B_DIM;
    int ch = idx / (H_DIM * B_DIM);

    const __half* gp = g + (size_t)b * N_OUT + j;
    float c = 0.f, P = 1.f;
    int t0b = ch * TC;
    for (int t0 = t0b; t0 < t0b + TC; t0 += 4) {
        float zt[4], fs[4];
#pragma unroll
        for (int u = 0; u < 4; u++) {
            size_t base = (size_t)(t0 + u) * B_DIM * N_OUT;
            zt[u] = __half2float(gp[base]);
            fs[u] = __half2float(gp[base + H_DIM]);
        }
#pragma unroll
        for (int u = 0; u < 4; u++) {
            c = fmaf(fs[u], zt[u] - c, c);
            P *= (1.f - fs[u]);
        }
    }
    Pc_buf[idx] = P;
    Cc_buf[idx] = c;
}

// ---------------- scan phase 2: prefix + re-scan, write h (fp16) + final c ----------------
__global__ __launch_bounds__(256)
void scan_phase2_kernel(const __half* __restrict__ g, __half* __restrict__ H,
                        float* __restrict__ out, int layer, int write_h) {
    int idx = blockIdx.x * 256 + threadIdx.x;
    if (idx >= NCH * B_DIM * H_DIM) return;
    int j = idx % H_DIM;
    int b = (idx / H_DIM) % B_DIM;
    int ch = idx / (H_DIM * B_DIM);

    float c = 0.f;
    for (int i = 0; i < ch; i++) {
        size_t o = ((size_t)i * B_DIM + b) * H_DIM + j;
        c = Cc_buf[o] + Pc_buf[o] * c;
    }

    const __half* gp = g + (size_t)b * N_OUT + j;
    int t0b = ch * TC;
    for (int t0 = t0b; t0 < t0b + TC; t0 += 4) {
        float zt[4], fs[4], os[4];
#pragma unroll
        for (int u = 0; u < 4; u++) {
            size_t base = (size_t)(t0 + u) * B_DIM * N_OUT;
            zt[u] = __half2float(gp[base]);
            fs[u] = __half2float(gp[base + H_DIM]);
            os[u] = __half2float(gp[base + 2 * H_DIM]);
        }
#pragma unroll
        for (int u = 0; u < 4; u++) {
            c = fmaf(fs[u], zt[u] - c, c);
            if (write_h)
                H[(size_t)((t0 + u) * B_DIM + b) * KPAD + j] = __float2half(os[u] * c);
        }
    }
    if (ch == NCH - 1)
        out[(size_t)b * (L_DIM * H_DIM) + (size_t)layer * H_DIM + j] = c;
}

// ---------------- launch ----------------
extern "C" void kernel_launch(void* const* d_in, const int* in_sizes, int n_in,
                              void* d_out, int out_size) {
    const float* sent = (const float*)d_in[0];
    const float* W0 = (const float*)d_in[2];
    const float* b0 = (const float*)d_in[3];
    const float* W1 = (const float*)d_in[4];
    const float* b1 = (const float*)d_in[5];
    const float* W2 = (const float*)d_in[6];
    const float* b2 = (const float*)d_in[7];
    float* out = (float*)d_out;

    __half* g;  cudaGetSymbolAddress((void**)&g, g_buf);
    __half *a0, *a12, *w0, *w1, *w2;
    cudaGetSymbolAddress((void**)&a0, A0_buf);
    cudaGetSymbolAddress((void**)&a12, A12_buf);
    cudaGetSymbolAddress((void**)&w0, W0_buf);
    cudaGetSymbolAddress((void**)&w1, W1_buf);
    cudaGetSymbolAddress((void**)&w2, W2_buf);

    cudaFuncSetAttribute(qrnn_gemm_kernel, cudaFuncAttributeMaxDynamicSharedMemorySize,
                         STAGES * STAGE_BYTES);

    dim3 wblk(32, 8);
    dim3 wgrid0(N_PADROWS / 32, KPAD0 / 32);
    dim3 wgrid12(N_PADROWS / 32, KPAD / 32);
    conv_w_kernel<<<wgrid0, wblk>>>(W0, w0, E_DIM, KPAD0);
    conv_w_kernel<<<wgrid12, wblk>>>(W1, w1, H_DIM, KPAD);
    conv_w_kernel<<<wgrid12, wblk>>>(W2, w2, H_DIM, KPAD);

    {
        int n = M_DIM * (KPAD0 / 4);
        conv_sent_kernel<<<(n + 255) / 256, 256>>>(sent);
    }

    dim3 ggrid(N_PADROWS / BN, M_DIM / BM);   // (19, 256)
    size_t smem = STAGES * STAGE_BYTES;
    int scan_total = NCH * B_DIM * H_DIM;
    int scan_blocks = (scan_total + 255) / 256;

    qrnn_gemm_kernel<<<ggrid, 256, smem>>>(a0, w0, KPAD0, KPAD0 / BK, b0, g);
    scan_phase1_kernel<<<scan_blocks, 256>>>(g);
    scan_phase2_kernel<<<scan_blocks, 256>>>(g, a12, out, 0, 1);

    qrnn_gemm_kernel<<<ggrid, 256, smem>>>(a12, w1, KPAD, KPAD / BK, b1, g);
    scan_phase1_kernel<<<scan_blocks, 256>>>(g);
    scan_phase2_kernel<<<scan_blocks, 256>>>(g, a12, out, 1, 1);

    qrnn_gemm_kernel<<<ggrid, 256, smem>>>(a12, w2, KPAD, KPAD / BK, b2, g);
    scan_phase1_kernel<<<scan_blocks, 256>>>(g);
    scan_phase2_kernel<<<scan_blocks, 256>>>(g, a12, out, 2, 0);
}

// round 10
// speedup vs baseline: 3.4854x; 1.1076x over previous
#include <cuda_runtime.h>
#include <cuda_fp16.h>
#include <cstdint>
#include <math.h>

// ---------------- problem constants ----------------
#define T_DIM 512
#define B_DIM 64
#define E_DIM 300
#define H_DIM 800
#define L_DIM 3
#define M_DIM (T_DIM * B_DIM)   // 32768
#define N_OUT 2400              // 3*H
#define N_PADROWS 2432          // N padded to mult of 128
#define KPAD0 320               // 300 -> mult of 64
#define KPAD  832               // 800 -> mult of 64

// scan chunking
#define NCH 16
#define TC  (T_DIM / NCH)       // 32

// GEMM tiling
#define BM 128
#define BN 128
#define BK 64
#define STAGES 3
#define STAGE_BYTES 32768       // A 16K | B 16K
#define A_OFF  0
#define B_OFF  16384

// ---------------- static scratch ----------------
__device__ __half g_buf[(size_t)M_DIM * N_OUT];           // post-activation z|f|o (fp16)
__device__ __half A0_buf[(size_t)M_DIM * KPAD0];          // layer0 A operand
__device__ __half A12_buf[(size_t)M_DIM * KPAD];          // layers 1/2 A operand (h); padding stays 0
__device__ __half W0_buf[(size_t)N_PADROWS * KPAD0];
__device__ __half W1_buf[(size_t)N_PADROWS * KPAD];
__device__ __half W2_buf[(size_t)N_PADROWS * KPAD];
__device__ float Pc_buf[(size_t)NCH * B_DIM * H_DIM];     // per-chunk product of (1-f)
__device__ float Cc_buf[(size_t)NCH * B_DIM * H_DIM];     // per-chunk local final c

// ---------------- helpers ----------------
__device__ __forceinline__ uint32_t smem_u32(const void* p) {
    uint32_t a;
    asm("{ .reg .u64 t; cvta.to.shared.u64 t, %1; cvt.u32.u64 %0, t; }" : "=r"(a) : "l"(p));
    return a;
}
__device__ __forceinline__ void cp16(uint32_t dst, const void* src) {
    asm volatile("cp.async.cg.shared.global [%0], [%1], 16;" :: "r"(dst), "l"(src) : "memory");
}
__device__ __forceinline__ void cp_commit() {
    asm volatile("cp.async.commit_group;" ::: "memory");
}
template <int N> __device__ __forceinline__ void cp_wait() {
    asm volatile("cp.async.wait_group %0;" :: "n"(N) : "memory");
}
__device__ __forceinline__ void ldsm4(uint32_t& r0, uint32_t& r1, uint32_t& r2, uint32_t& r3,
                                      uint32_t addr) {
    asm volatile("ldmatrix.sync.aligned.m8n8.x4.shared.b16 {%0,%1,%2,%3}, [%4];"
                 : "=r"(r0), "=r"(r1), "=r"(r2), "=r"(r3) : "r"(addr));
}
__device__ __forceinline__ void mma_f16(float* c, const uint32_t* a, const uint32_t* b) {
    asm volatile(
        "mma.sync.aligned.m16n8k16.row.col.f32.f16.f16.f32 "
        "{%0,%1,%2,%3}, {%4,%5,%6,%7}, {%8,%9}, {%0,%1,%2,%3};"
        : "+f"(c[0]), "+f"(c[1]), "+f"(c[2]), "+f"(c[3])
        : "r"(a[0]), "r"(a[1]), "r"(a[2]), "r"(a[3]), "r"(b[0]), "r"(b[1]));
}
__device__ __forceinline__ float sigmoidf_(float x) { return 1.f / (1.f + __expf(-x)); }

// f16x2 fast activations (1 MUFU per 2 elements)
__device__ __forceinline__ uint32_t tanh_h2(uint32_t x) {
    uint32_t r;
    asm("tanh.approx.f16x2 %0, %1;" : "=r"(r) : "r"(x));
    return r;
}
__device__ __forceinline__ uint32_t pack_h2(float a, float b) {
    __half2 h = __floats2half2_rn(a, b);
    return *reinterpret_cast<uint32_t*>(&h);
}
// sigmoid(x) = 0.5*tanh(0.5x) + 0.5 (exact identity)
__device__ __forceinline__ uint32_t sigmoid_h2(uint32_t x) {
    const __half2 half_c = __floats2half2_rn(0.5f, 0.5f);
    __half2 xh = *reinterpret_cast<__half2*>(&x);
    __half2 t = __hmul2(xh, half_c);
    uint32_t tu = tanh_h2(*reinterpret_cast<uint32_t*>(&t));
    __half2 th = *reinterpret_cast<__half2*>(&tu);
    __half2 r = __hfma2(th, half_c, half_c);
    return *reinterpret_cast<uint32_t*>(&r);
}

// ---------------- weight transpose fp16: W[K,N] -> Wt[Np,Kp] ----------------
__global__ void conv_w_kernel(const float* __restrict__ W,
                              __half* __restrict__ Tw, int K, int Kp) {
    __shared__ float tile[32][33];
    int kb = blockIdx.y * 32, nb = blockIdx.x * 32;
    for (int r = threadIdx.y; r < 32; r += 8) {
        int k = kb + r, n = nb + threadIdx.x;
        tile[r][threadIdx.x] = (k < K && n < N_OUT) ? W[(size_t)k * N_OUT + n] : 0.f;
    }
    __syncthreads();
    for (int r = threadIdx.y; r < 32; r += 8) {
        int n = nb + r, k = kb + threadIdx.x;
        Tw[(size_t)n * Kp + k] = __float2half(tile[threadIdx.x][r]);
    }
}

// ---------------- sent fp32 -> fp16 (padded K), vectorized ----------------
__global__ void conv_sent_kernel(const float* __restrict__ x) {
    int i = blockIdx.x * 256 + threadIdx.x;
    if (i >= M_DIM * (KPAD0 / 4)) return;
    int row = i / (KPAD0 / 4);
    int j4 = (i % (KPAD0 / 4)) * 4;
    uint2 outv;
    if (j4 < E_DIM) {
        float4 v = *reinterpret_cast<const float4*>(x + (size_t)row * E_DIM + j4);
        __half2 h0 = __floats2half2_rn(v.x, v.y);
        __half2 h1 = __floats2half2_rn(v.z, v.w);
        outv.x = *reinterpret_cast<uint32_t*>(&h0);
        outv.y = *reinterpret_cast<uint32_t*>(&h1);
    } else {
        outv.x = 0u; outv.y = 0u;
    }
    *reinterpret_cast<uint2*>(&A0_buf[(size_t)row * KPAD0 + j4]) = outv;
}

// ---------------- fp16 HMMA GEMM (128x128 tile, BK=64) with fused bias + activation ----
// g[m,n] = act( sum_k A[m,k]*W[n,k] + bias[n] ), stored fp16
__global__ __launch_bounds__(256, 2)
void qrnn_gemm_kernel(const __half* __restrict__ A, const __half* __restrict__ B,
                      int ldk, int nc,
                      const float* __restrict__ bias, __half* __restrict__ C) {
    extern __shared__ char smem[];
    const uint32_t sbase = smem_u32(smem);

    const int tid = threadIdx.x;
    const int lane = tid & 31;
    const int wid = tid >> 5;
    const int wm = wid >> 2;          // 0..1 -> 64-row slabs
    const int wn = wid & 3;           // 0..3 -> 32-col slabs
    const int am0 = blockIdx.y * BM;
    const int bn0 = blockIdx.x * BN;

    auto load_stage = [&](int kc, int st) {
        const size_t kof = (size_t)kc * BK;
        uint32_t sb = sbase + st * STAGE_BYTES;
#pragma unroll
        for (int i = 0; i < 4; i++) {
            int id = tid + i * 256;            // 0..1023
            int row = id >> 3, c = id & 7;
            int sc = c ^ (row & 7);
            uint32_t soff = row * 128 + sc * 16;
            cp16(sb + A_OFF + soff, A + (size_t)(am0 + row) * ldk + kof + (size_t)c * 8);
            cp16(sb + B_OFF + soff, B + (size_t)(bn0 + row) * ldk + kof + (size_t)c * 8);
        }
    };

    float acc[4][4][4];
#pragma unroll
    for (int i = 0; i < 4; i++)
#pragma unroll
        for (int j = 0; j < 4; j++)
#pragma unroll
            for (int q = 0; q < 4; q++) acc[i][j][q] = 0.f;

    load_stage(0, 0); cp_commit();
    if (nc > 1) { load_stage(1, 1); cp_commit(); }

    const int lr = lane & 15;
    const int lc = lane >> 4;

    for (int kc = 0; kc < nc; kc++) {
        if (kc + 1 < nc) cp_wait<1>(); else cp_wait<0>();
        __syncthreads();
        if (kc + 2 < nc) { load_stage(kc + 2, (kc + 2) % STAGES); cp_commit(); }

        uint32_t sb = sbase + (kc % STAGES) * STAGE_BYTES;
#pragma unroll
        for (int kp = 0; kp < 2; kp++) {
            uint32_t breg[2][4][2];
#pragma unroll
            for (int kk2 = 0; kk2 < 2; kk2++) {
                int kk = kp * 2 + kk2;
#pragma unroll
                for (int p = 0; p < 2; p++) {
                    int rowb = wn * 32 + p * 16 + lr;
                    uint32_t off = rowb * 128 + (((kk * 2 + lc) ^ (rowb & 7)) * 16);
                    uint32_t r0, r1, r2, r3;
                    ldsm4(r0, r1, r2, r3, sb + B_OFF + off);
                    breg[kk2][2 * p][0] = r0; breg[kk2][2 * p + 1][0] = r1;
                    breg[kk2][2 * p][1] = r2; breg[kk2][2 * p + 1][1] = r3;
                }
            }
#pragma unroll
            for (int kk2 = 0; kk2 < 2; kk2++) {
                int kk = kp * 2 + kk2;
#pragma unroll
                for (int mt = 0; mt < 4; mt++) {
                    int rowa = wm * 64 + mt * 16 + lr;
                    uint32_t off = rowa * 128 + (((kk * 2 + lc) ^ (rowa & 7)) * 16);
                    uint32_t a[4];
                    ldsm4(a[0], a[1], a[2], a[3], sb + A_OFF + off);
#pragma unroll
                    for (int ng = 0; ng < 4; ng++)
                        mma_f16(acc[mt][ng], a, breg[kk2][ng]);
                }
            }
        }
    }

    // ---- epilogue: bias + f16x2 activation, half2 stores ----
    const int tg = lane >> 2;
    const int tq = lane & 3;
#pragma unroll
    for (int ng = 0; ng < 4; ng++) {
        int colb = bn0 + wn * 32 + ng * 8;
        if (colb >= N_OUT) continue;
        int col = colb + tq * 2;
        float2 bv = *reinterpret_cast<const float2*>(&bias[col]);
        bool is_t = colb < H_DIM;     // uniform per ng group (8-col blocks, H=800)
#pragma unroll
        for (int mt = 0; mt < 4; mt++) {
            int r0 = am0 + wm * 64 + mt * 16 + tg;
            uint32_t p0 = pack_h2(acc[mt][ng][0] + bv.x, acc[mt][ng][1] + bv.y);
            uint32_t p1 = pack_h2(acc[mt][ng][2] + bv.x, acc[mt][ng][3] + bv.y);
            uint32_t v0 = is_t ? tanh_h2(p0) : sigmoid_h2(p0);
            uint32_t v1 = is_t ? tanh_h2(p1) : sigmoid_h2(p1);
            *reinterpret_cast<uint32_t*>(&C[(size_t)r0 * N_OUT + col]) = v0;
            *reinterpret_cast<uint32_t*>(&C[(size_t)(r0 + 8) * N_OUT + col]) = v1;
        }
    }
}

// ---------------- scan phase 1: per-chunk (prod(1-f), local c) ----------------
__global__ __launch_bounds__(256)
void scan_phase1_kernel(const __half* __restrict__ g) {
    int idx = blockIdx.x * 256 + threadIdx.x;
    if (idx >= NCH * B_DIM * H_DIM) return;
    int j = idx % H_DIM;
    int b = (idx / H_DIM) % B_DIM;
    int ch = idx / (H_DIM * B_DIM);

    const __half* gp = g + (size_t)b * N_OUT + j;
    float c = 0.f, P = 1.f;
    int t0b = ch * TC;
    for (int t0 = t0b; t0 < t0b + TC; t0 += 4) {
        float zt[4], fs[4];
#pragma unroll
        for (int u = 0; u < 4; u++) {
            size_t base = (size_t)(t0 + u) * B_DIM * N_OUT;
            zt[u] = __half2float(gp[base]);
            fs[u] = __half2float(gp[base + H_DIM]);
        }
#pragma unroll
        for (int u = 0; u < 4; u++) {
            c = fmaf(fs[u], zt[u] - c, c);
            P *= (1.f - fs[u]);
        }
    }
    Pc_buf[idx] = P;
    Cc_buf[idx] = c;
}

// ---------------- scan phase 2: prefix + re-scan, write h (fp16) + final c ----------------
__global__ __launch_bounds__(256)
void scan_phase2_kernel(const __half* __restrict__ g, __half* __restrict__ H,
                        float* __restrict__ out, int layer, int write_h) {
    int idx = blockIdx.x * 256 + threadIdx.x;
    if (idx >= NCH * B_DIM * H_DIM) return;
    int j = idx % H_DIM;
    int b = (idx / H_DIM) % B_DIM;
    int ch = idx / (H_DIM * B_DIM);

    float c = 0.f;
    for (int i = 0; i < ch; i++) {
        size_t o = ((size_t)i * B_DIM + b) * H_DIM + j;
        c = Cc_buf[o] + Pc_buf[o] * c;
    }

    const __half* gp = g + (size_t)b * N_OUT + j;
    int t0b = ch * TC;
    for (int t0 = t0b; t0 < t0b + TC; t0 += 4) {
        float zt[4], fs[4], os[4];
#pragma unroll
        for (int u = 0; u < 4; u++) {
            size_t base = (size_t)(t0 + u) * B_DIM * N_OUT;
            zt[u] = __half2float(gp[base]);
            fs[u] = __half2float(gp[base + H_DIM]);
            os[u] = __half2float(gp[base + 2 * H_DIM]);
        }
#pragma unroll
        for (int u = 0; u < 4; u++) {
            c = fmaf(fs[u], zt[u] - c, c);
            if (write_h)
                H[(size_t)((t0 + u) * B_DIM + b) * KPAD + j] = __float2half(os[u] * c);
        }
    }
    if (ch == NCH - 1)
        out[(size_t)b * (L_DIM * H_DIM) + (size_t)layer * H_DIM + j] = c;
}

// ---------------- launch ----------------
extern "C" void kernel_launch(void* const* d_in, const int* in_sizes, int n_in,
                              void* d_out, int out_size) {
    const float* sent = (const float*)d_in[0];
    const float* W0 = (const float*)d_in[2];
    const float* b0 = (const float*)d_in[3];
    const float* W1 = (const float*)d_in[4];
    const float* b1 = (const float*)d_in[5];
    const float* W2 = (const float*)d_in[6];
    const float* b2 = (const float*)d_in[7];
    float* out = (float*)d_out;

    __half* g;  cudaGetSymbolAddress((void**)&g, g_buf);
    __half *a0, *a12, *w0, *w1, *w2;
    cudaGetSymbolAddress((void**)&a0, A0_buf);
    cudaGetSymbolAddress((void**)&a12, A12_buf);
    cudaGetSymbolAddress((void**)&w0, W0_buf);
    cudaGetSymbolAddress((void**)&w1, W1_buf);
    cudaGetSymbolAddress((void**)&w2, W2_buf);

    cudaFuncSetAttribute(qrnn_gemm_kernel, cudaFuncAttributeMaxDynamicSharedMemorySize,
                         STAGES * STAGE_BYTES);

    dim3 wblk(32, 8);
    dim3 wgrid0(N_PADROWS / 32, KPAD0 / 32);
    dim3 wgrid12(N_PADROWS / 32, KPAD / 32);
    conv_w_kernel<<<wgrid0, wblk>>>(W0, w0, E_DIM, KPAD0);
    conv_w_kernel<<<wgrid12, wblk>>>(W1, w1, H_DIM, KPAD);
    conv_w_kernel<<<wgrid12, wblk>>>(W2, w2, H_DIM, KPAD);

    {
        int n = M_DIM * (KPAD0 / 4);
        conv_sent_kernel<<<(n + 255) / 256, 256>>>(sent);
    }

    dim3 ggrid(N_PADROWS / BN, M_DIM / BM);   // (19, 256)
    size_t smem = STAGES * STAGE_BYTES;
    int scan_total = NCH * B_DIM * H_DIM;
    int scan_blocks = (scan_total + 255) / 256;

    qrnn_gemm_kernel<<<ggrid, 256, smem>>>(a0, w0, KPAD0, KPAD0 / BK, b0, g);
    scan_phase1_kernel<<<scan_blocks, 256>>>(g);
    scan_phase2_kernel<<<scan_blocks, 256>>>(g, a12, out, 0, 1);

    qrnn_gemm_kernel<<<ggrid, 256, smem>>>(a12, w1, KPAD, KPAD / BK, b1, g);
    scan_phase1_kernel<<<scan_blocks, 256>>>(g);
    scan_phase2_kernel<<<scan_blocks, 256>>>(g, a12, out, 1, 1);

    qrnn_gemm_kernel<<<ggrid, 256, smem>>>(a12, w2, KPAD, KPAD / BK, b2, g);
    scan_phase1_kernel<<<scan_blocks, 256>>>(g);
    scan_phase2_kernel<<<scan_blocks, 256>>>(g, a12, out, 2, 0);
}

// round 11
// speedup vs baseline: 3.6401x; 1.0444x over previous
#include <cuda_runtime.h>
#include <cuda_fp16.h>
#include <cstdint>
#include <math.h>

// ---------------- problem constants ----------------
#define T_DIM 512
#define B_DIM 64
#define E_DIM 300
#define H_DIM 800
#define H2    (H_DIM / 2)        // 400 half2 pairs
#define L_DIM 3
#define M_DIM (T_DIM * B_DIM)   // 32768
#define N_OUT 2400              // 3*H
#define N_PADROWS 2432          // N padded to mult of 128
#define KPAD0 320               // 300 -> mult of 64
#define KPAD  832               // 800 -> mult of 64

// scan chunking
#define NCH 16
#define TC  (T_DIM / NCH)       // 32

// GEMM tiling
#define BM 128
#define BN 128
#define BK 64
#define STAGES 3
#define STAGE_BYTES 32768       // A 16K | B 16K
#define A_OFF  0
#define B_OFF  16384

// ---------------- static scratch ----------------
__device__ __half g_buf[(size_t)M_DIM * N_OUT];           // post-activation z|f|o (fp16)
__device__ __half A0_buf[(size_t)M_DIM * KPAD0];          // layer0 A operand
__device__ __half A12_buf[(size_t)M_DIM * KPAD];          // layers 1/2 A operand (h); padding stays 0
__device__ __half W0_buf[(size_t)N_PADROWS * KPAD0];
__device__ __half W1_buf[(size_t)N_PADROWS * KPAD];
__device__ __half W2_buf[(size_t)N_PADROWS * KPAD];
__device__ float2 Pc_buf[(size_t)NCH * B_DIM * H2];       // per-chunk product of (1-f), j-pairs
__device__ float2 Cc_buf[(size_t)NCH * B_DIM * H2];       // per-chunk local final c, j-pairs

// ---------------- helpers ----------------
__device__ __forceinline__ uint32_t smem_u32(const void* p) {
    uint32_t a;
    asm("{ .reg .u64 t; cvta.to.shared.u64 t, %1; cvt.u32.u64 %0, t; }" : "=r"(a) : "l"(p));
    return a;
}
__device__ __forceinline__ void cp16(uint32_t dst, const void* src) {
    asm volatile("cp.async.cg.shared.global [%0], [%1], 16;" :: "r"(dst), "l"(src) : "memory");
}
__device__ __forceinline__ void cp_commit() {
    asm volatile("cp.async.commit_group;" ::: "memory");
}
template <int N> __device__ __forceinline__ void cp_wait() {
    asm volatile("cp.async.wait_group %0;" :: "n"(N) : "memory");
}
__device__ __forceinline__ void ldsm4(uint32_t& r0, uint32_t& r1, uint32_t& r2, uint32_t& r3,
                                      uint32_t addr) {
    asm volatile("ldmatrix.sync.aligned.m8n8.x4.shared.b16 {%0,%1,%2,%3}, [%4];"
                 : "=r"(r0), "=r"(r1), "=r"(r2), "=r"(r3) : "r"(addr));
}
__device__ __forceinline__ void mma_f16(float* c, const uint32_t* a, const uint32_t* b) {
    asm volatile(
        "mma.sync.aligned.m16n8k16.row.col.f32.f16.f16.f32 "
        "{%0,%1,%2,%3}, {%4,%5,%6,%7}, {%8,%9}, {%0,%1,%2,%3};"
        : "+f"(c[0]), "+f"(c[1]), "+f"(c[2]), "+f"(c[3])
        : "r"(a[0]), "r"(a[1]), "r"(a[2]), "r"(a[3]), "r"(b[0]), "r"(b[1]));
}

// f16x2 fast activations (1 MUFU per 2 elements)
__device__ __forceinline__ uint32_t tanh_h2(uint32_t x) {
    uint32_t r;
    asm("tanh.approx.f16x2 %0, %1;" : "=r"(r) : "r"(x));
    return r;
}
__device__ __forceinline__ uint32_t pack_h2(float a, float b) {
    __half2 h = __floats2half2_rn(a, b);
    return *reinterpret_cast<uint32_t*>(&h);
}
// sigmoid(x) = 0.5*tanh(0.5x) + 0.5 (exact identity)
__device__ __forceinline__ uint32_t sigmoid_h2(uint32_t x) {
    const __half2 half_c = __floats2half2_rn(0.5f, 0.5f);
    __half2 xh = *reinterpret_cast<__half2*>(&x);
    __half2 t = __hmul2(xh, half_c);
    uint32_t tu = tanh_h2(*reinterpret_cast<uint32_t*>(&t));
    __half2 th = *reinterpret_cast<__half2*>(&tu);
    __half2 r = __hfma2(th, half_c, half_c);
    return *reinterpret_cast<uint32_t*>(&r);
}

// ---------------- weight transpose fp16: W[K,N] -> Wt[Np,Kp] ----------------
__global__ void conv_w_kernel(const float* __restrict__ W,
                              __half* __restrict__ Tw, int K, int Kp) {
    __shared__ float tile[32][33];
    int kb = blockIdx.y * 32, nb = blockIdx.x * 32;
    for (int r = threadIdx.y; r < 32; r += 8) {
        int k = kb + r, n = nb + threadIdx.x;
        tile[r][threadIdx.x] = (k < K && n < N_OUT) ? W[(size_t)k * N_OUT + n] : 0.f;
    }
    __syncthreads();
    for (int r = threadIdx.y; r < 32; r += 8) {
        int n = nb + r, k = kb + threadIdx.x;
        Tw[(size_t)n * Kp + k] = __float2half(tile[threadIdx.x][r]);
    }
}

// ---------------- sent fp32 -> fp16 (padded K), vectorized ----------------
__global__ void conv_sent_kernel(const float* __restrict__ x) {
    int i = blockIdx.x * 256 + threadIdx.x;
    if (i >= M_DIM * (KPAD0 / 4)) return;
    int row = i / (KPAD0 / 4);
    int j4 = (i % (KPAD0 / 4)) * 4;
    uint2 outv;
    if (j4 < E_DIM) {
        float4 v = *reinterpret_cast<const float4*>(x + (size_t)row * E_DIM + j4);
        __half2 h0 = __floats2half2_rn(v.x, v.y);
        __half2 h1 = __floats2half2_rn(v.z, v.w);
        outv.x = *reinterpret_cast<uint32_t*>(&h0);
        outv.y = *reinterpret_cast<uint32_t*>(&h1);
    } else {
        outv.x = 0u; outv.y = 0u;
    }
    *reinterpret_cast<uint2*>(&A0_buf[(size_t)row * KPAD0 + j4]) = outv;
}

// ---------------- fp16 HMMA GEMM (128x128 tile, BK=64) with fused bias + activation ----
__global__ __launch_bounds__(256, 2)
void qrnn_gemm_kernel(const __half* __restrict__ A, const __half* __restrict__ B,
                      int ldk, int nc,
                      const float* __restrict__ bias, __half* __restrict__ C) {
    extern __shared__ char smem[];
    const uint32_t sbase = smem_u32(smem);

    const int tid = threadIdx.x;
    const int lane = tid & 31;
    const int wid = tid >> 5;
    const int wm = wid >> 2;
    const int wn = wid & 3;
    const int am0 = blockIdx.y * BM;
    const int bn0 = blockIdx.x * BN;

    auto load_stage = [&](int kc, int st) {
        const size_t kof = (size_t)kc * BK;
        uint32_t sb = sbase + st * STAGE_BYTES;
#pragma unroll
        for (int i = 0; i < 4; i++) {
            int id = tid + i * 256;
            int row = id >> 3, c = id & 7;
            int sc = c ^ (row & 7);
            uint32_t soff = row * 128 + sc * 16;
            cp16(sb + A_OFF + soff, A + (size_t)(am0 + row) * ldk + kof + (size_t)c * 8);
            cp16(sb + B_OFF + soff, B + (size_t)(bn0 + row) * ldk + kof + (size_t)c * 8);
        }
    };

    float acc[4][4][4];
#pragma unroll
    for (int i = 0; i < 4; i++)
#pragma unroll
        for (int j = 0; j < 4; j++)
#pragma unroll
            for (int q = 0; q < 4; q++) acc[i][j][q] = 0.f;

    load_stage(0, 0); cp_commit();
    if (nc > 1) { load_stage(1, 1); cp_commit(); }

    const int lr = lane & 15;
    const int lc = lane >> 4;

    for (int kc = 0; kc < nc; kc++) {
        if (kc + 1 < nc) cp_wait<1>(); else cp_wait<0>();
        __syncthreads();
        if (kc + 2 < nc) { load_stage(kc + 2, (kc + 2) % STAGES); cp_commit(); }

        uint32_t sb = sbase + (kc % STAGES) * STAGE_BYTES;
#pragma unroll
        for (int kp = 0; kp < 2; kp++) {
            uint32_t breg[2][4][2];
#pragma unroll
            for (int kk2 = 0; kk2 < 2; kk2++) {
                int kk = kp * 2 + kk2;
#pragma unroll
                for (int p = 0; p < 2; p++) {
                    int rowb = wn * 32 + p * 16 + lr;
                    uint32_t off = rowb * 128 + (((kk * 2 + lc) ^ (rowb & 7)) * 16);
                    uint32_t r0, r1, r2, r3;
                    ldsm4(r0, r1, r2, r3, sb + B_OFF + off);
                    breg[kk2][2 * p][0] = r0; breg[kk2][2 * p + 1][0] = r1;
                    breg[kk2][2 * p][1] = r2; breg[kk2][2 * p + 1][1] = r3;
                }
            }
#pragma unroll
            for (int kk2 = 0; kk2 < 2; kk2++) {
                int kk = kp * 2 + kk2;
#pragma unroll
                for (int mt = 0; mt < 4; mt++) {
                    int rowa = wm * 64 + mt * 16 + lr;
                    uint32_t off = rowa * 128 + (((kk * 2 + lc) ^ (rowa & 7)) * 16);
                    uint32_t a[4];
                    ldsm4(a[0], a[1], a[2], a[3], sb + A_OFF + off);
#pragma unroll
                    for (int ng = 0; ng < 4; ng++)
                        mma_f16(acc[mt][ng], a, breg[kk2][ng]);
                }
            }
        }
    }

    // ---- epilogue: bias + f16x2 activation, half2 stores ----
    const int tg = lane >> 2;
    const int tq = lane & 3;
#pragma unroll
    for (int ng = 0; ng < 4; ng++) {
        int colb = bn0 + wn * 32 + ng * 8;
        if (colb >= N_OUT) continue;
        int col = colb + tq * 2;
        float2 bv = *reinterpret_cast<const float2*>(&bias[col]);
        bool is_t = colb < H_DIM;
#pragma unroll
        for (int mt = 0; mt < 4; mt++) {
            int r0 = am0 + wm * 64 + mt * 16 + tg;
            uint32_t p0 = pack_h2(acc[mt][ng][0] + bv.x, acc[mt][ng][1] + bv.y);
            uint32_t p1 = pack_h2(acc[mt][ng][2] + bv.x, acc[mt][ng][3] + bv.y);
            uint32_t v0 = is_t ? tanh_h2(p0) : sigmoid_h2(p0);
            uint32_t v1 = is_t ? tanh_h2(p1) : sigmoid_h2(p1);
            *reinterpret_cast<uint32_t*>(&C[(size_t)r0 * N_OUT + col]) = v0;
            *reinterpret_cast<uint32_t*>(&C[(size_t)(r0 + 8) * N_OUT + col]) = v1;
        }
    }
}

// ---------------- scan phase 1 (half2 lanes): per-chunk (prod(1-f), local c) --------
__global__ __launch_bounds__(256)
void scan_phase1_kernel(const __half* __restrict__ g) {
    int idx = blockIdx.x * 256 + threadIdx.x;
    if (idx >= NCH * B_DIM * H2) return;
    int j2 = idx % H2;
    int b = (idx / H2) % B_DIM;
    int ch = idx / (H2 * B_DIM);

    const __half* gp = g + (size_t)b * N_OUT + 2 * j2;
    float2 c = make_float2(0.f, 0.f);
    float2 P = make_float2(1.f, 1.f);
    int t0b = ch * TC;
    for (int t0 = t0b; t0 < t0b + TC; t0 += 4) {
        float2 zt[4], fs[4];
#pragma unroll
        for (int u = 0; u < 4; u++) {
            size_t base = (size_t)(t0 + u) * B_DIM * N_OUT;
            zt[u] = __half22float2(*reinterpret_cast<const __half2*>(gp + base));
            fs[u] = __half22float2(*reinterpret_cast<const __half2*>(gp + base + H_DIM));
        }
#pragma unroll
        for (int u = 0; u < 4; u++) {
            c.x = fmaf(fs[u].x, zt[u].x - c.x, c.x);
            c.y = fmaf(fs[u].y, zt[u].y - c.y, c.y);
            P.x *= (1.f - fs[u].x);
            P.y *= (1.f - fs[u].y);
        }
    }
    Pc_buf[idx] = P;
    Cc_buf[idx] = c;
}

// ---------------- scan phase 2 (half2 lanes): prefix + re-scan ----------------
__global__ __launch_bounds__(256)
void scan_phase2_kernel(const __half* __restrict__ g, __half* __restrict__ H,
                        float* __restrict__ out, int layer, int write_h) {
    int idx = blockIdx.x * 256 + threadIdx.x;
    if (idx >= NCH * B_DIM * H2) return;
    int j2 = idx % H2;
    int b = (idx / H2) % B_DIM;
    int ch = idx / (H2 * B_DIM);

    float2 c = make_float2(0.f, 0.f);
    for (int i = 0; i < ch; i++) {
        size_t o = ((size_t)i * B_DIM + b) * H2 + j2;
        float2 Ci = Cc_buf[o];
        float2 Pi = Pc_buf[o];
        c.x = Ci.x + Pi.x * c.x;
        c.y = Ci.y + Pi.y * c.y;
    }

    const __half* gp = g + (size_t)b * N_OUT + 2 * j2;
    int t0b = ch * TC;
    for (int t0 = t0b; t0 < t0b + TC; t0 += 4) {
        float2 zt[4], fs[4], os[4];
#pragma unroll
        for (int u = 0; u < 4; u++) {
            size_t base = (size_t)(t0 + u) * B_DIM * N_OUT;
            zt[u] = __half22float2(*reinterpret_cast<const __half2*>(gp + base));
            fs[u] = __half22float2(*reinterpret_cast<const __half2*>(gp + base + H_DIM));
            os[u] = __half22float2(*reinterpret_cast<const __half2*>(gp + base + 2 * H_DIM));
        }
#pragma unroll
        for (int u = 0; u < 4; u++) {
            c.x = fmaf(fs[u].x, zt[u].x - c.x, c.x);
            c.y = fmaf(fs[u].y, zt[u].y - c.y, c.y);
            if (write_h) {
                __half2 hv = __floats2half2_rn(os[u].x * c.x, os[u].y * c.y);
                *reinterpret_cast<__half2*>(
                    &H[(size_t)((t0 + u) * B_DIM + b) * KPAD + 2 * j2]) = hv;
            }
        }
    }
    if (ch == NCH - 1) {
        *reinterpret_cast<float2*>(
            &out[(size_t)b * (L_DIM * H_DIM) + (size_t)layer * H_DIM + 2 * j2]) = c;
    }
}

// ---------------- launch ----------------
extern "C" void kernel_launch(void* const* d_in, const int* in_sizes, int n_in,
                              void* d_out, int out_size) {
    const float* sent = (const float*)d_in[0];
    const float* W0 = (const float*)d_in[2];
    const float* b0 = (const float*)d_in[3];
    const float* W1 = (const float*)d_in[4];
    const float* b1 = (const float*)d_in[5];
    const float* W2 = (const float*)d_in[6];
    const float* b2 = (const float*)d_in[7];
    float* out = (float*)d_out;

    __half* g;  cudaGetSymbolAddress((void**)&g, g_buf);
    __half *a0, *a12, *w0, *w1, *w2;
    cudaGetSymbolAddress((void**)&a0, A0_buf);
    cudaGetSymbolAddress((void**)&a12, A12_buf);
    cudaGetSymbolAddress((void**)&w0, W0_buf);
    cudaGetSymbolAddress((void**)&w1, W1_buf);
    cudaGetSymbolAddress((void**)&w2, W2_buf);

    cudaFuncSetAttribute(qrnn_gemm_kernel, cudaFuncAttributeMaxDynamicSharedMemorySize,
                         STAGES * STAGE_BYTES);

    dim3 wblk(32, 8);
    dim3 wgrid0(N_PADROWS / 32, KPAD0 / 32);
    dim3 wgrid12(N_PADROWS / 32, KPAD / 32);
    conv_w_kernel<<<wgrid0, wblk>>>(W0, w0, E_DIM, KPAD0);
    conv_w_kernel<<<wgrid12, wblk>>>(W1, w1, H_DIM, KPAD);
    conv_w_kernel<<<wgrid12, wblk>>>(W2, w2, H_DIM, KPAD);

    {
        int n = M_DIM * (KPAD0 / 4);
        conv_sent_kernel<<<(n + 255) / 256, 256>>>(sent);
    }

    dim3 ggrid(N_PADROWS / BN, M_DIM / BM);   // (19, 256)
    size_t smem = STAGES * STAGE_BYTES;
    int scan_total = NCH * B_DIM * H2;        // 409600
    int scan_blocks = (scan_total + 255) / 256;

    qrnn_gemm_kernel<<<ggrid, 256, smem>>>(a0, w0, KPAD0, KPAD0 / BK, b0, g);
    scan_phase1_kernel<<<scan_blocks, 256>>>(g);
    scan_phase2_kernel<<<scan_blocks, 256>>>(g, a12, out, 0, 1);

    qrnn_gemm_kernel<<<ggrid, 256, smem>>>(a12, w1, KPAD, KPAD / BK, b1, g);
    scan_phase1_kernel<<<scan_blocks, 256>>>(g);
    scan_phase2_kernel<<<scan_blocks, 256>>>(g, a12, out, 1, 1);

    qrnn_gemm_kernel<<<ggrid, 256, smem>>>(a12, w2, KPAD, KPAD / BK, b2, g);
    scan_phase1_kernel<<<scan_blocks, 256>>>(g);
    scan_phase2_kernel<<<scan_blocks, 256>>>(g, a12, out, 2, 0);
}

// round 12
// speedup vs baseline: 3.7433x; 1.0283x over previous
#include <cuda_runtime.h>
#include <cuda_fp16.h>
#include <cstdint>
#include <math.h>

// ---------------- problem constants ----------------
#define T_DIM 512
#define B_DIM 64
#define E_DIM 300
#define H_DIM 800
#define H2    (H_DIM / 2)        // 400 half2 pairs
#define L_DIM 3
#define M_DIM (T_DIM * B_DIM)   // 32768
#define N_OUT 2400              // 3*H
#define N_PADROWS 2432          // N padded to mult of 128
#define KPAD0 320               // 300 -> mult of 64
#define KPAD  832               // 800 -> mult of 64

// fused scan: 16 j2-pairs x 16 t-chunks of 32
#define SJ 16
#define SCH 16
#define STC (T_DIM / SCH)       // 32

// GEMM tiling
#define BM 128
#define BN 128
#define BK 64
#define STAGES 3
#define STAGE_BYTES 32768       // A 16K | B 16K
#define A_OFF  0
#define B_OFF  16384

// ---------------- static scratch ----------------
__device__ __half g_buf[(size_t)M_DIM * N_OUT];           // post-activation z|f|o (fp16)
__device__ __half A0_buf[(size_t)M_DIM * KPAD0];          // layer0 A operand
__device__ __half A12_buf[(size_t)M_DIM * KPAD];          // layers 1/2 A operand (h); padding stays 0
__device__ __half W0_buf[(size_t)N_PADROWS * KPAD0];
__device__ __half W1_buf[(size_t)N_PADROWS * KPAD];
__device__ __half W2_buf[(size_t)N_PADROWS * KPAD];

// ---------------- helpers ----------------
__device__ __forceinline__ uint32_t smem_u32(const void* p) {
    uint32_t a;
    asm("{ .reg .u64 t; cvta.to.shared.u64 t, %1; cvt.u32.u64 %0, t; }" : "=r"(a) : "l"(p));
    return a;
}
__device__ __forceinline__ void cp16(uint32_t dst, const void* src) {
    asm volatile("cp.async.cg.shared.global [%0], [%1], 16;" :: "r"(dst), "l"(src) : "memory");
}
__device__ __forceinline__ void cp_commit() {
    asm volatile("cp.async.commit_group;" ::: "memory");
}
template <int N> __device__ __forceinline__ void cp_wait() {
    asm volatile("cp.async.wait_group %0;" :: "n"(N) : "memory");
}
__device__ __forceinline__ void ldsm4(uint32_t& r0, uint32_t& r1, uint32_t& r2, uint32_t& r3,
                                      uint32_t addr) {
    asm volatile("ldmatrix.sync.aligned.m8n8.x4.shared.b16 {%0,%1,%2,%3}, [%4];"
                 : "=r"(r0), "=r"(r1), "=r"(r2), "=r"(r3) : "r"(addr));
}
__device__ __forceinline__ void mma_f16(float* c, const uint32_t* a, const uint32_t* b) {
    asm volatile(
        "mma.sync.aligned.m16n8k16.row.col.f32.f16.f16.f32 "
        "{%0,%1,%2,%3}, {%4,%5,%6,%7}, {%8,%9}, {%0,%1,%2,%3};"
        : "+f"(c[0]), "+f"(c[1]), "+f"(c[2]), "+f"(c[3])
        : "r"(a[0]), "r"(a[1]), "r"(a[2]), "r"(a[3]), "r"(b[0]), "r"(b[1]));
}

// f16x2 fast activations (1 MUFU per 2 elements)
__device__ __forceinline__ uint32_t tanh_h2(uint32_t x) {
    uint32_t r;
    asm("tanh.approx.f16x2 %0, %1;" : "=r"(r) : "r"(x));
    return r;
}
__device__ __forceinline__ uint32_t pack_h2(float a, float b) {
    __half2 h = __floats2half2_rn(a, b);
    return *reinterpret_cast<uint32_t*>(&h);
}
// sigmoid(x) = 0.5*tanh(0.5x) + 0.5 (exact identity)
__device__ __forceinline__ uint32_t sigmoid_h2(uint32_t x) {
    const __half2 half_c = __floats2half2_rn(0.5f, 0.5f);
    __half2 xh = *reinterpret_cast<__half2*>(&x);
    __half2 t = __hmul2(xh, half_c);
    uint32_t tu = tanh_h2(*reinterpret_cast<uint32_t*>(&t));
    __half2 th = *reinterpret_cast<__half2*>(&tu);
    __half2 r = __hfma2(th, half_c, half_c);
    return *reinterpret_cast<uint32_t*>(&r);
}

// ---------------- weight transpose fp16 (all 3 layers in one launch) ----------------
__global__ void conv_w_all_kernel(const float* __restrict__ W0, const float* __restrict__ W1,
                                  const float* __restrict__ W2,
                                  __half* __restrict__ T0, __half* __restrict__ T1,
                                  __half* __restrict__ T2) {
    __shared__ float tile[32][33];
    int layer = blockIdx.z;
    const float* W = (layer == 0) ? W0 : (layer == 1) ? W1 : W2;
    __half* Tw = (layer == 0) ? T0 : (layer == 1) ? T1 : T2;
    int K = (layer == 0) ? E_DIM : H_DIM;
    int Kp = (layer == 0) ? KPAD0 : KPAD;
    int kb = blockIdx.y * 32, nb = blockIdx.x * 32;
    if (kb >= Kp) return;
    for (int r = threadIdx.y; r < 32; r += 8) {
        int k = kb + r, n = nb + threadIdx.x;
        tile[r][threadIdx.x] = (k < K && n < N_OUT) ? W[(size_t)k * N_OUT + n] : 0.f;
    }
    __syncthreads();
    for (int r = threadIdx.y; r < 32; r += 8) {
        int n = nb + r, k = kb + threadIdx.x;
        Tw[(size_t)n * Kp + k] = __float2half(tile[threadIdx.x][r]);
    }
}

// ---------------- sent fp32 -> fp16 (padded K), vectorized ----------------
__global__ void conv_sent_kernel(const float* __restrict__ x) {
    int i = blockIdx.x * 256 + threadIdx.x;
    if (i >= M_DIM * (KPAD0 / 4)) return;
    int row = i / (KPAD0 / 4);
    int j4 = (i % (KPAD0 / 4)) * 4;
    uint2 outv;
    if (j4 < E_DIM) {
        float4 v = *reinterpret_cast<const float4*>(x + (size_t)row * E_DIM + j4);
        __half2 h0 = __floats2half2_rn(v.x, v.y);
        __half2 h1 = __floats2half2_rn(v.z, v.w);
        outv.x = *reinterpret_cast<uint32_t*>(&h0);
        outv.y = *reinterpret_cast<uint32_t*>(&h1);
    } else {
        outv.x = 0u; outv.y = 0u;
    }
    *reinterpret_cast<uint2*>(&A0_buf[(size_t)row * KPAD0 + j4]) = outv;
}

// ---------------- fp16 HMMA GEMM (128x128 tile, BK=64) with fused bias + activation ----
__global__ __launch_bounds__(256, 2)
void qrnn_gemm_kernel(const __half* __restrict__ A, const __half* __restrict__ B,
                      int ldk, int nc,
                      const float* __restrict__ bias, __half* __restrict__ C) {
    extern __shared__ char smem[];
    const uint32_t sbase = smem_u32(smem);

    const int tid = threadIdx.x;
    const int lane = tid & 31;
    const int wid = tid >> 5;
    const int wm = wid >> 2;
    const int wn = wid & 3;
    const int am0 = blockIdx.y * BM;
    const int bn0 = blockIdx.x * BN;

    auto load_stage = [&](int kc, int st) {
        const size_t kof = (size_t)kc * BK;
        uint32_t sb = sbase + st * STAGE_BYTES;
#pragma unroll
        for (int i = 0; i < 4; i++) {
            int id = tid + i * 256;
            int row = id >> 3, c = id & 7;
            int sc = c ^ (row & 7);
            uint32_t soff = row * 128 + sc * 16;
            cp16(sb + A_OFF + soff, A + (size_t)(am0 + row) * ldk + kof + (size_t)c * 8);
            cp16(sb + B_OFF + soff, B + (size_t)(bn0 + row) * ldk + kof + (size_t)c * 8);
        }
    };

    float acc[4][4][4];
#pragma unroll
    for (int i = 0; i < 4; i++)
#pragma unroll
        for (int j = 0; j < 4; j++)
#pragma unroll
            for (int q = 0; q < 4; q++) acc[i][j][q] = 0.f;

    load_stage(0, 0); cp_commit();
    if (nc > 1) { load_stage(1, 1); cp_commit(); }

    const int lr = lane & 15;
    const int lc = lane >> 4;

    for (int kc = 0; kc < nc; kc++) {
        if (kc + 1 < nc) cp_wait<1>(); else cp_wait<0>();
        __syncthreads();
        if (kc + 2 < nc) { load_stage(kc + 2, (kc + 2) % STAGES); cp_commit(); }

        uint32_t sb = sbase + (kc % STAGES) * STAGE_BYTES;
#pragma unroll
        for (int kp = 0; kp < 2; kp++) {
            uint32_t breg[2][4][2];
#pragma unroll
            for (int kk2 = 0; kk2 < 2; kk2++) {
                int kk = kp * 2 + kk2;
#pragma unroll
                for (int p = 0; p < 2; p++) {
                    int rowb = wn * 32 + p * 16 + lr;
                    uint32_t off = rowb * 128 + (((kk * 2 + lc) ^ (rowb & 7)) * 16);
                    uint32_t r0, r1, r2, r3;
                    ldsm4(r0, r1, r2, r3, sb + B_OFF + off);
                    breg[kk2][2 * p][0] = r0; breg[kk2][2 * p + 1][0] = r1;
                    breg[kk2][2 * p][1] = r2; breg[kk2][2 * p + 1][1] = r3;
                }
            }
#pragma unroll
            for (int kk2 = 0; kk2 < 2; kk2++) {
                int kk = kp * 2 + kk2;
#pragma unroll
                for (int mt = 0; mt < 4; mt++) {
                    int rowa = wm * 64 + mt * 16 + lr;
                    uint32_t off = rowa * 128 + (((kk * 2 + lc) ^ (rowa & 7)) * 16);
                    uint32_t a[4];
                    ldsm4(a[0], a[1], a[2], a[3], sb + A_OFF + off);
#pragma unroll
                    for (int ng = 0; ng < 4; ng++)
                        mma_f16(acc[mt][ng], a, breg[kk2][ng]);
                }
            }
        }
    }

    // ---- epilogue: bias + f16x2 activation, half2 stores ----
    const int tg = lane >> 2;
    const int tq = lane & 3;
#pragma unroll
    for (int ng = 0; ng < 4; ng++) {
        int colb = bn0 + wn * 32 + ng * 8;
        if (colb >= N_OUT) continue;
        int col = colb + tq * 2;
        float2 bv = *reinterpret_cast<const float2*>(&bias[col]);
        bool is_t = colb < H_DIM;
#pragma unroll
        for (int mt = 0; mt < 4; mt++) {
            int r0 = am0 + wm * 64 + mt * 16 + tg;
            uint32_t p0 = pack_h2(acc[mt][ng][0] + bv.x, acc[mt][ng][1] + bv.y);
            uint32_t p1 = pack_h2(acc[mt][ng][2] + bv.x, acc[mt][ng][3] + bv.y);
            uint32_t v0 = is_t ? tanh_h2(p0) : sigmoid_h2(p0);
            uint32_t v1 = is_t ? tanh_h2(p1) : sigmoid_h2(p1);
            *reinterpret_cast<uint32_t*>(&C[(size_t)r0 * N_OUT + col]) = v0;
            *reinterpret_cast<uint32_t*>(&C[(size_t)(r0 + 8) * N_OUT + col]) = v1;
        }
    }
}

// ---------------- fused fo-pool scan: one kernel, block-local two-pass ----------------
// block = (b, 16 j2-pairs) x T=512; threads = 16 j2 (tid&15) x 16 chunks of 32 (tid>>4).
// Identical per-lane arithmetic + prefix order to the previous two-kernel version.
__global__ __launch_bounds__(256)
void qrnn_scan_fused_kernel(const __half* __restrict__ g, __half* __restrict__ H,
                            float* __restrict__ out, int layer, int write_h) {
    __shared__ float2 Pv[SCH][SJ];
    __shared__ float2 Cv[SCH][SJ];

    const int jl = threadIdx.x & 15;
    const int ch = threadIdx.x >> 4;          // 0..15
    const int j2 = blockIdx.x * SJ + jl;      // < H2 (400 = 25*16)
    const int b = blockIdx.y;

    const __half* gp = g + (size_t)b * N_OUT + 2 * j2;
    const int t0b = ch * STC;

    // phase A: local chunk summary (P, c)
    float2 c = make_float2(0.f, 0.f);
    float2 P = make_float2(1.f, 1.f);
    for (int t0 = t0b; t0 < t0b + STC; t0 += 4) {
        float2 zt[4], fs[4];
#pragma unroll
        for (int u = 0; u < 4; u++) {
            size_t base = (size_t)(t0 + u) * B_DIM * N_OUT;
            zt[u] = __half22float2(*reinterpret_cast<const __half2*>(gp + base));
            fs[u] = __half22float2(*reinterpret_cast<const __half2*>(gp + base + H_DIM));
        }
#pragma unroll
        for (int u = 0; u < 4; u++) {
            c.x = fmaf(fs[u].x, zt[u].x - c.x, c.x);
            c.y = fmaf(fs[u].y, zt[u].y - c.y, c.y);
            P.x *= (1.f - fs[u].x);
            P.y *= (1.f - fs[u].y);
        }
    }
    Pv[ch][jl] = P;
    Cv[ch][jl] = c;
    __syncthreads();

    // exclusive prefix over chunk summaries (same serial order as before)
    c = make_float2(0.f, 0.f);
    for (int i = 0; i < ch; i++) {
        float2 Ci = Cv[i][jl];
        float2 Pi = Pv[i][jl];
        c.x = Ci.x + Pi.x * c.x;
        c.y = Ci.y + Pi.y * c.y;
    }

    // phase B: re-scan with correct entering state, write h
    for (int t0 = t0b; t0 < t0b + STC; t0 += 4) {
        float2 zt[4], fs[4], os[4];
#pragma unroll
        for (int u = 0; u < 4; u++) {
            size_t base = (size_t)(t0 + u) * B_DIM * N_OUT;
            zt[u] = __half22float2(*reinterpret_cast<const __half2*>(gp + base));
            fs[u] = __half22float2(*reinterpret_cast<const __half2*>(gp + base + H_DIM));
            os[u] = __half22float2(*reinterpret_cast<const __half2*>(gp + base + 2 * H_DIM));
        }
#pragma unroll
        for (int u = 0; u < 4; u++) {
            c.x = fmaf(fs[u].x, zt[u].x - c.x, c.x);
            c.y = fmaf(fs[u].y, zt[u].y - c.y, c.y);
            if (write_h) {
                __half2 hv = __floats2half2_rn(os[u].x * c.x, os[u].y * c.y);
                *reinterpret_cast<__half2*>(
                    &H[(size_t)((t0 + u) * B_DIM + b) * KPAD + 2 * j2]) = hv;
            }
        }
    }
    if (ch == SCH - 1) {
        *reinterpret_cast<float2*>(
            &out[(size_t)b * (L_DIM * H_DIM) + (size_t)layer * H_DIM + 2 * j2]) = c;
    }
}

// ---------------- launch ----------------
extern "C" void kernel_launch(void* const* d_in, const int* in_sizes, int n_in,
                              void* d_out, int out_size) {
    const float* sent = (const float*)d_in[0];
    const float* W0 = (const float*)d_in[2];
    const float* b0 = (const float*)d_in[3];
    const float* W1 = (const float*)d_in[4];
    const float* b1 = (const float*)d_in[5];
    const float* W2 = (const float*)d_in[6];
    const float* b2 = (const float*)d_in[7];
    float* out = (float*)d_out;

    __half* g;  cudaGetSymbolAddress((void**)&g, g_buf);
    __half *a0, *a12, *w0, *w1, *w2;
    cudaGetSymbolAddress((void**)&a0, A0_buf);
    cudaGetSymbolAddress((void**)&a12, A12_buf);
    cudaGetSymbolAddress((void**)&w0, W0_buf);
    cudaGetSymbolAddress((void**)&w1, W1_buf);
    cudaGetSymbolAddress((void**)&w2, W2_buf);

    cudaFuncSetAttribute(qrnn_gemm_kernel, cudaFuncAttributeMaxDynamicSharedMemorySize,
                         STAGES * STAGE_BYTES);

    {
        dim3 wblk(32, 8);
        dim3 wgrid(N_PADROWS / 32, KPAD / 32, 3);   // layer 0 early-exits beyond KPAD0
        conv_w_all_kernel<<<wgrid, wblk>>>(W0, W1, W2, w0, w1, w2);
    }
    {
        int n = M_DIM * (KPAD0 / 4);
        conv_sent_kernel<<<(n + 255) / 256, 256>>>(sent);
    }

    dim3 ggrid(N_PADROWS / BN, M_DIM / BM);   // (19, 256)
    size_t smem = STAGES * STAGE_BYTES;
    dim3 sgrid(H2 / SJ, B_DIM);               // (25, 64)

    qrnn_gemm_kernel<<<ggrid, 256, smem>>>(a0, w0, KPAD0, KPAD0 / BK, b0, g);
    qrnn_scan_fused_kernel<<<sgrid, 256>>>(g, a12, out, 0, 1);

    qrnn_gemm_kernel<<<ggrid, 256, smem>>>(a12, w1, KPAD, KPAD / BK, b1, g);
    qrnn_scan_fused_kernel<<<sgrid, 256>>>(g, a12, out, 1, 1);

    qrnn_gemm_kernel<<<ggrid, 256, smem>>>(a12, w2, KPAD, KPAD / BK, b2, g);
    qrnn_scan_fused_kernel<<<sgrid, 256>>>(g, a12, out, 2, 0);
}

// round 13
// speedup vs baseline: 3.7734x; 1.0080x over previous
#include <cuda_runtime.h>
#include <cuda_fp16.h>
#include <cstdint>
#include <math.h>

// ---------------- problem constants ----------------
#define T_DIM 512
#define B_DIM 64
#define E_DIM 300
#define H_DIM 800
#define H2    (H_DIM / 2)        // 400 half2 pairs
#define L_DIM 3
#define M_DIM (T_DIM * B_DIM)   // 32768
#define N_OUT 2400              // 3*H
#define N_PADROWS 2432          // N padded to mult of 128
#define KPAD0 320               // 300 -> mult of 64
#define KPAD  832               // 800 -> mult of 64

// fused scan: 16 j2-pairs x 16 t-chunks of 32
#define SJ 16
#define SCH 16
#define STC (T_DIM / SCH)       // 32

// GEMM tiling
#define BM 128
#define BN 128
#define BK 64
#define STAGES 3
#define STAGE_BYTES 32768       // A 16K | B 16K
#define A_OFF  0
#define B_OFF  16384

// ---------------- static scratch ----------------
__device__ __half g_buf[(size_t)M_DIM * N_OUT];           // post-activation z|f|o (fp16)
__device__ __half A0_buf[(size_t)M_DIM * KPAD0];          // layer0 A operand
__device__ __half A12_buf[(size_t)M_DIM * KPAD];          // layers 1/2 A operand (h); padding stays 0
__device__ __half W0_buf[(size_t)N_PADROWS * KPAD0];
__device__ __half W1_buf[(size_t)N_PADROWS * KPAD];
__device__ __half W2_buf[(size_t)N_PADROWS * KPAD];

// ---------------- helpers ----------------
__device__ __forceinline__ uint32_t smem_u32(const void* p) {
    uint32_t a;
    asm("{ .reg .u64 t; cvta.to.shared.u64 t, %1; cvt.u32.u64 %0, t; }" : "=r"(a) : "l"(p));
    return a;
}
__device__ __forceinline__ void cp16(uint32_t dst, const void* src) {
    asm volatile("cp.async.cg.shared.global [%0], [%1], 16;" :: "r"(dst), "l"(src) : "memory");
}
__device__ __forceinline__ void cp_commit() {
    asm volatile("cp.async.commit_group;" ::: "memory");
}
template <int N> __device__ __forceinline__ void cp_wait() {
    asm volatile("cp.async.wait_group %0;" :: "n"(N) : "memory");
}
__device__ __forceinline__ void ldsm4(uint32_t& r0, uint32_t& r1, uint32_t& r2, uint32_t& r3,
                                      uint32_t addr) {
    asm volatile("ldmatrix.sync.aligned.m8n8.x4.shared.b16 {%0,%1,%2,%3}, [%4];"
                 : "=r"(r0), "=r"(r1), "=r"(r2), "=r"(r3) : "r"(addr));
}
__device__ __forceinline__ void mma_f16(float* c, const uint32_t* a, const uint32_t* b) {
    asm volatile(
        "mma.sync.aligned.m16n8k16.row.col.f32.f16.f16.f32 "
        "{%0,%1,%2,%3}, {%4,%5,%6,%7}, {%8,%9}, {%0,%1,%2,%3};"
        : "+f"(c[0]), "+f"(c[1]), "+f"(c[2]), "+f"(c[3])
        : "r"(a[0]), "r"(a[1]), "r"(a[2]), "r"(a[3]), "r"(b[0]), "r"(b[1]));
}

// f16x2 fast activations (1 MUFU per 2 elements)
__device__ __forceinline__ uint32_t tanh_h2(uint32_t x) {
    uint32_t r;
    asm("tanh.approx.f16x2 %0, %1;" : "=r"(r) : "r"(x));
    return r;
}
__device__ __forceinline__ uint32_t pack_h2(float a, float b) {
    __half2 h = __floats2half2_rn(a, b);
    return *reinterpret_cast<uint32_t*>(&h);
}
// sigmoid(x) = 0.5*tanh(0.5x) + 0.5 (exact identity)
__device__ __forceinline__ uint32_t sigmoid_h2(uint32_t x) {
    const __half2 half_c = __floats2half2_rn(0.5f, 0.5f);
    __half2 xh = *reinterpret_cast<__half2*>(&x);
    __half2 t = __hmul2(xh, half_c);
    uint32_t tu = tanh_h2(*reinterpret_cast<uint32_t*>(&t));
    __half2 th = *reinterpret_cast<__half2*>(&tu);
    __half2 r = __hfma2(th, half_c, half_c);
    return *reinterpret_cast<uint32_t*>(&r);
}

// ---------------- weight transpose fp16 (all 3 layers in one launch) ----------------
__global__ void conv_w_all_kernel(const float* __restrict__ W0, const float* __restrict__ W1,
                                  const float* __restrict__ W2,
                                  __half* __restrict__ T0, __half* __restrict__ T1,
                                  __half* __restrict__ T2) {
    __shared__ float tile[32][33];
    int layer = blockIdx.z;
    const float* W = (layer == 0) ? W0 : (layer == 1) ? W1 : W2;
    __half* Tw = (layer == 0) ? T0 : (layer == 1) ? T1 : T2;
    int K = (layer == 0) ? E_DIM : H_DIM;
    int Kp = (layer == 0) ? KPAD0 : KPAD;
    int kb = blockIdx.y * 32, nb = blockIdx.x * 32;
    if (kb >= Kp) return;
    for (int r = threadIdx.y; r < 32; r += 8) {
        int k = kb + r, n = nb + threadIdx.x;
        tile[r][threadIdx.x] = (k < K && n < N_OUT) ? W[(size_t)k * N_OUT + n] : 0.f;
    }
    __syncthreads();
    for (int r = threadIdx.y; r < 32; r += 8) {
        int n = nb + r, k = kb + threadIdx.x;
        Tw[(size_t)n * Kp + k] = __float2half(tile[threadIdx.x][r]);
    }
}

// ---------------- sent fp32 -> fp16 (padded K), vectorized ----------------
__global__ void conv_sent_kernel(const float* __restrict__ x) {
    int i = blockIdx.x * 256 + threadIdx.x;
    if (i >= M_DIM * (KPAD0 / 4)) return;
    int row = i / (KPAD0 / 4);
    int j4 = (i % (KPAD0 / 4)) * 4;
    uint2 outv;
    if (j4 < E_DIM) {
        float4 v = *reinterpret_cast<const float4*>(x + (size_t)row * E_DIM + j4);
        __half2 h0 = __floats2half2_rn(v.x, v.y);
        __half2 h1 = __floats2half2_rn(v.z, v.w);
        outv.x = *reinterpret_cast<uint32_t*>(&h0);
        outv.y = *reinterpret_cast<uint32_t*>(&h1);
    } else {
        outv.x = 0u; outv.y = 0u;
    }
    *reinterpret_cast<uint2*>(&A0_buf[(size_t)row * KPAD0 + j4]) = outv;
}

// ---------------- fp16 HMMA GEMM (128x128 tile, BK=64), hoisted addressing ----------
__global__ __launch_bounds__(256, 2)
void qrnn_gemm_kernel(const __half* __restrict__ A, const __half* __restrict__ B,
                      int ldk, int nc,
                      const float* __restrict__ bias, __half* __restrict__ C) {
    extern __shared__ char smem[];
    const uint32_t sbase = smem_u32(smem);

    const int tid = threadIdx.x;
    const int lane = tid & 31;
    const int wid = tid >> 5;
    const int wm = wid >> 2;
    const int wn = wid & 3;
    const int am0 = blockIdx.y * BM;
    const int bn0 = blockIdx.x * BN;

    // ---- hoisted loader offsets (kc-invariant) ----
    uint32_t ld_soff[4];      // smem offsets (same for A and B planes)
    uint32_t ld_goffA[4];     // global element offsets (excl. k)
    uint32_t ld_goffB[4];
#pragma unroll
    for (int i = 0; i < 4; i++) {
        int id = tid + i * 256;
        int row = id >> 3, c = id & 7;
        int sc = c ^ (row & 7);
        ld_soff[i] = row * 128 + sc * 16;
        ld_goffA[i] = (uint32_t)((am0 + row) * ldk + c * 8);
        ld_goffB[i] = (uint32_t)((bn0 + row) * ldk + c * 8);
    }

    auto load_stage = [&](int kc, int st) {
        const uint32_t kof = (uint32_t)kc * BK;
        uint32_t sb = sbase + st * STAGE_BYTES;
#pragma unroll
        for (int i = 0; i < 4; i++) {
            cp16(sb + A_OFF + ld_soff[i], A + ld_goffA[i] + kof);
            cp16(sb + B_OFF + ld_soff[i], B + ld_goffB[i] + kof);
        }
    };

    // ---- hoisted ldsm offsets: rowa&7 == lr&7 (mt*16, slabs are mult of 8) ----
    const int lr = lane & 15;
    const int lc = lane >> 4;
    uint32_t swz[4];          // kk-dependent swizzle term, row-independent
#pragma unroll
    for (int kk = 0; kk < 4; kk++)
        swz[kk] = (uint32_t)(((kk * 2 + lc) ^ (lr & 7)) * 16);
    const uint32_t rowbaseA = (uint32_t)((wm * 64 + lr) * 128);      // + mt*2048
    const uint32_t rowbaseB = (uint32_t)((wn * 32 + lr) * 128);      // + p*2048

    float acc[4][4][4];
#pragma unroll
    for (int i = 0; i < 4; i++)
#pragma unroll
        for (int j = 0; j < 4; j++)
#pragma unroll
            for (int q = 0; q < 4; q++) acc[i][j][q] = 0.f;

    load_stage(0, 0); cp_commit();
    if (nc > 1) { load_stage(1, 1); cp_commit(); }

    int st_cur = 0, st_pre = 2;   // stage of kc, stage for kc+2
    for (int kc = 0; kc < nc; kc++) {
        if (kc + 1 < nc) cp_wait<1>(); else cp_wait<0>();
        __syncthreads();
        if (kc + 2 < nc) {
            load_stage(kc + 2, st_pre); cp_commit();
        }

        const uint32_t sbA = sbase + st_cur * STAGE_BYTES + A_OFF + rowbaseA;
        const uint32_t sbB = sbase + st_cur * STAGE_BYTES + B_OFF + rowbaseB;
        if (++st_cur == STAGES) st_cur = 0;
        if (++st_pre == STAGES) st_pre = 0;

#pragma unroll
        for (int kp = 0; kp < 2; kp++) {
            uint32_t breg[2][4][2];
#pragma unroll
            for (int kk2 = 0; kk2 < 2; kk2++) {
                const uint32_t sw = swz[kp * 2 + kk2];
#pragma unroll
                for (int p = 0; p < 2; p++) {
                    uint32_t r0, r1, r2, r3;
                    ldsm4(r0, r1, r2, r3, sbB + p * 2048 + sw);
                    breg[kk2][2 * p][0] = r0; breg[kk2][2 * p + 1][0] = r1;
                    breg[kk2][2 * p][1] = r2; breg[kk2][2 * p + 1][1] = r3;
                }
            }
#pragma unroll
            for (int kk2 = 0; kk2 < 2; kk2++) {
                const uint32_t sw = swz[kp * 2 + kk2];
#pragma unroll
                for (int mt = 0; mt < 4; mt++) {
                    uint32_t a[4];
                    ldsm4(a[0], a[1], a[2], a[3], sbA + mt * 2048 + sw);
#pragma unroll
                    for (int ng = 0; ng < 4; ng++)
                        mma_f16(acc[mt][ng], a, breg[kk2][ng]);
                }
            }
        }
    }

    // ---- epilogue: bias + f16x2 activation, half2 stores ----
    const int tg = lane >> 2;
    const int tq = lane & 3;
#pragma unroll
    for (int ng = 0; ng < 4; ng++) {
        int colb = bn0 + wn * 32 + ng * 8;
        if (colb >= N_OUT) continue;
        int col = colb + tq * 2;
        float2 bv = *reinterpret_cast<const float2*>(&bias[col]);
        bool is_t = colb < H_DIM;
#pragma unroll
        for (int mt = 0; mt < 4; mt++) {
            int r0 = am0 + wm * 64 + mt * 16 + tg;
            uint32_t p0 = pack_h2(acc[mt][ng][0] + bv.x, acc[mt][ng][1] + bv.y);
            uint32_t p1 = pack_h2(acc[mt][ng][2] + bv.x, acc[mt][ng][3] + bv.y);
            uint32_t v0 = is_t ? tanh_h2(p0) : sigmoid_h2(p0);
            uint32_t v1 = is_t ? tanh_h2(p1) : sigmoid_h2(p1);
            *reinterpret_cast<uint32_t*>(&C[(size_t)r0 * N_OUT + col]) = v0;
            *reinterpret_cast<uint32_t*>(&C[(size_t)(r0 + 8) * N_OUT + col]) = v1;
        }
    }
}

// ---------------- fused fo-pool scan: one kernel, block-local two-pass ----------------
__global__ __launch_bounds__(256)
void qrnn_scan_fused_kernel(const __half* __restrict__ g, __half* __restrict__ H,
                            float* __restrict__ out, int layer, int write_h) {
    __shared__ float2 Pv[SCH][SJ];
    __shared__ float2 Cv[SCH][SJ];

    const int jl = threadIdx.x & 15;
    const int ch = threadIdx.x >> 4;
    const int j2 = blockIdx.x * SJ + jl;
    const int b = blockIdx.y;

    const __half* gp = g + (size_t)b * N_OUT + 2 * j2;
    const int t0b = ch * STC;

    float2 c = make_float2(0.f, 0.f);
    float2 P = make_float2(1.f, 1.f);
    for (int t0 = t0b; t0 < t0b + STC; t0 += 4) {
        float2 zt[4], fs[4];
#pragma unroll
        for (int u = 0; u < 4; u++) {
            size_t base = (size_t)(t0 + u) * B_DIM * N_OUT;
            zt[u] = __half22float2(*reinterpret_cast<const __half2*>(gp + base));
            fs[u] = __half22float2(*reinterpret_cast<const __half2*>(gp + base + H_DIM));
        }
#pragma unroll
        for (int u = 0; u < 4; u++) {
            c.x = fmaf(fs[u].x, zt[u].x - c.x, c.x);
            c.y = fmaf(fs[u].y, zt[u].y - c.y, c.y);
            P.x *= (1.f - fs[u].x);
            P.y *= (1.f - fs[u].y);
        }
    }
    Pv[ch][jl] = P;
    Cv[ch][jl] = c;
    __syncthreads();

    c = make_float2(0.f, 0.f);
    for (int i = 0; i < ch; i++) {
        float2 Ci = Cv[i][jl];
        float2 Pi = Pv[i][jl];
        c.x = Ci.x + Pi.x * c.x;
        c.y = Ci.y + Pi.y * c.y;
    }

    for (int t0 = t0b; t0 < t0b + STC; t0 += 4) {
        float2 zt[4], fs[4], os[4];
#pragma unroll
        for (int u = 0; u < 4; u++) {
            size_t base = (size_t)(t0 + u) * B_DIM * N_OUT;
            zt[u] = __half22float2(*reinterpret_cast<const __half2*>(gp + base));
            fs[u] = __half22float2(*reinterpret_cast<const __half2*>(gp + base + H_DIM));
            os[u] = __half22float2(*reinterpret_cast<const __half2*>(gp + base + 2 * H_DIM));
        }
#pragma unroll
        for (int u = 0; u < 4; u++) {
            c.x = fmaf(fs[u].x, zt[u].x - c.x, c.x);
            c.y = fmaf(fs[u].y, zt[u].y - c.y, c.y);
            if (write_h) {
                __half2 hv = __floats2half2_rn(os[u].x * c.x, os[u].y * c.y);
                *reinterpret_cast<__half2*>(
                    &H[(size_t)((t0 + u) * B_DIM + b) * KPAD + 2 * j2]) = hv;
            }
        }
    }
    if (ch == SCH - 1) {
        *reinterpret_cast<float2*>(
            &out[(size_t)b * (L_DIM * H_DIM) + (size_t)layer * H_DIM + 2 * j2]) = c;
    }
}

// ---------------- launch ----------------
extern "C" void kernel_launch(void* const* d_in, const int* in_sizes, int n_in,
                              void* d_out, int out_size) {
    const float* sent = (const float*)d_in[0];
    const float* W0 = (const float*)d_in[2];
    const float* b0 = (const float*)d_in[3];
    const float* W1 = (const float*)d_in[4];
    const float* b1 = (const float*)d_in[5];
    const float* W2 = (const float*)d_in[6];
    const float* b2 = (const float*)d_in[7];
    float* out = (float*)d_out;

    __half* g;  cudaGetSymbolAddress((void**)&g, g_buf);
    __half *a0, *a12, *w0, *w1, *w2;
    cudaGetSymbolAddress((void**)&a0, A0_buf);
    cudaGetSymbolAddress((void**)&a12, A12_buf);
    cudaGetSymbolAddress((void**)&w0, W0_buf);
    cudaGetSymbolAddress((void**)&w1, W1_buf);
    cudaGetSymbolAddress((void**)&w2, W2_buf);

    cudaFuncSetAttribute(qrnn_gemm_kernel, cudaFuncAttributeMaxDynamicSharedMemorySize,
                         STAGES * STAGE_BYTES);

    {
        dim3 wblk(32, 8);
        dim3 wgrid(N_PADROWS / 32, KPAD / 32, 3);
        conv_w_all_kernel<<<wgrid, wblk>>>(W0, W1, W2, w0, w1, w2);
    }
    {
        int n = M_DIM * (KPAD0 / 4);
        conv_sent_kernel<<<(n + 255) / 256, 256>>>(sent);
    }

    dim3 ggrid(N_PADROWS / BN, M_DIM / BM);   // (19, 256)
    size_t smem = STAGES * STAGE_BYTES;
    dim3 sgrid(H2 / SJ, B_DIM);               // (25, 64)

    qrnn_gemm_kernel<<<ggrid, 256, smem>>>(a0, w0, KPAD0, KPAD0 / BK, b0, g);
    qrnn_scan_fused_kernel<<<sgrid, 256>>>(g, a12, out, 0, 1);

    qrnn_gemm_kernel<<<ggrid, 256, smem>>>(a12, w1, KPAD, KPAD / BK, b1, g);
    qrnn_scan_fused_kernel<<<sgrid, 256>>>(g, a12, out, 1, 1);

    qrnn_gemm_kernel<<<ggrid, 256, smem>>>(a12, w2, KPAD, KPAD / BK, b2, g);
    qrnn_scan_fused_kernel<<<sgrid, 256>>>(g, a12, out, 2, 0);
}